// round 13
// baseline (speedup 1.0000x reference)
#include <cuda_runtime.h>
#include <cuda_bf16.h>
#include <cstdint>
#include <math.h>

// ---------------- problem constants ----------------
#define BATCH   2
#define SEQL    2048
#define MTOK    (BATCH*SEQL)      // 4096
#define DMODEL  1024
#define DINNER  2048
#define NHEADS  32
#define HEADD   64
#define NSTATE  128
#define BCCOLS  16384             // 32 heads * 512 used cols
#define NTOT3   (BCCOLS + 128)    // GEMM3 N incl. folded dt block
#define XPROJ_ROWSTRIDE 513       // x_proj_w has 513 rows per head; last unused

// ---------------- fp32 scratch ----------------
__device__ float  g_x  [(size_t)MTOK*DINNER];     // silu(x)
__device__ float  g_z  [(size_t)MTOK*DINNER];     // raw z
__device__ float  g_dt [(size_t)MTOK*NHEADS];     // softplus(dt)  (folded into GEMM3)
__device__ float  g_bc [(size_t)MTOK*BCCOLS];     // raw BC (per-head 512 cols)
__device__ float2 g_a  [(size_t)BATCH*NHEADS*SEQL*NSTATE]; // abar
__device__ float2 g_u  [(size_t)BATCH*NHEADS*SEQL*NSTATE]; // u_in
__device__ float2 g_c  [(size_t)BATCH*NHEADS*SEQL*NSTATE]; // Cc
__device__ float  g_yp [(size_t)MTOK*NHEADS*4];   // 4-way partial y_red

// ---------------- bf16 hi/lo-split operand scratch (K' = 3K) ----------------
__device__ __nv_bfloat16 g_uA [(size_t)MTOK * 3*DMODEL];    // A' for GEMM1
__device__ __nv_bfloat16 g_w1 [(size_t)(2*DINNER) * 3*DMODEL];
__device__ __nv_bfloat16 g_xA [(size_t)MTOK * 3*DINNER];    // A' for GEMM3
__device__ __nv_bfloat16 g_w3 [(size_t)NTOT3 * 3*DINNER];   // remapped x_proj_w + dtw fold
__device__ __nv_bfloat16 g_yA [(size_t)MTOK * 3*DINNER];    // A' for GEMM4 (ymul-fused)
__device__ __nv_bfloat16 g_w4 [(size_t)DMODEL * 3*DINNER];

// ---------------- helpers ----------------
__device__ __forceinline__ float siluf(float v) { return v / (1.0f + expf(-v)); }
__device__ __forceinline__ float softplusf(float v) { return (v > 20.0f) ? v : log1pf(expf(v)); }

__device__ __forceinline__ uint32_t smem_u32(const void* p) {
    uint32_t a;
    asm("{ .reg .u64 t; cvta.to.shared.u64 t, %1; cvt.u32.u64 %0, t; }" : "=r"(a) : "l"(p));
    return a;
}

__device__ __forceinline__ void ldsm4(uint32_t* r, uint32_t addr) {
    asm volatile("ldmatrix.sync.aligned.m8n8.x4.shared.b16 {%0,%1,%2,%3}, [%4];"
        : "=r"(r[0]), "=r"(r[1]), "=r"(r[2]), "=r"(r[3]) : "r"(addr));
}

__device__ __forceinline__ void mma16816(float* d, const uint32_t* a, uint32_t b0, uint32_t b1) {
    asm volatile("mma.sync.aligned.m16n8k16.row.col.f32.bf16.bf16.f32 "
        "{%0,%1,%2,%3}, {%4,%5,%6,%7}, {%8,%9}, {%0,%1,%2,%3};"
        : "+f"(d[0]), "+f"(d[1]), "+f"(d[2]), "+f"(d[3])
        : "r"(a[0]), "r"(a[1]), "r"(a[2]), "r"(a[3]), "r"(b0), "r"(b1));
}

#define CP_ASYNC16(dst, src) \
    asm volatile("cp.async.cg.shared.global [%0], [%1], 16;" :: "r"(dst), "l"(src) : "memory")
#define CP_COMMIT() asm volatile("cp.async.commit_group;" ::: "memory")
#define CP_WAIT1()  asm volatile("cp.async.wait_group 1;" ::: "memory")

__device__ __forceinline__ void split_store3(__nv_bfloat16* base, size_t off, size_t seg,
                                             float v0, float v1) {
    __nv_bfloat16 h0 = __float2bfloat16(v0), h1 = __float2bfloat16(v1);
    __nv_bfloat16 l0 = __float2bfloat16(v0 - __bfloat162float(h0));
    __nv_bfloat16 l1 = __float2bfloat16(v1 - __bfloat162float(h1));
    __nv_bfloat162 hh = {h0, h1}, ll = {l0, l1};
    *(__nv_bfloat162*)(base + off)           = hh;   // hi
    *(__nv_bfloat162*)(base + off + seg)     = ll;   // lo
    *(__nv_bfloat162*)(base + off + 2 * seg) = hh;   // hi  (A-pattern [hi|lo|hi])
}

// ============ HMMA bf16 GEMM: BM=256, BN=128, BK=64, warp tile 64x64 ============
// 256 threads (8 warps = 4M x 2N), 3 stages x 48KB (144KB dyn smem, 1 CTA/SM).
// Per k16 sub-step: 8 LDSM -> 32 MMA (4:1, was 2.67:1) -> LSU pressure cut ~40%.
// fp32 accumulate (acc = 128 regs/thread). Loop skeleton identical to R12.
// Swizzle: 128B rows, chunk c ^ (row&7); LDSM addr = (row*128 + ((row&7)<<4)) ^ kcs.
// EPI 0: plain fp32 store (ldc = N).
// EPI 1: in_proj: n0<DINNER -> C0=silu(v); else C1=v.
// EPI 2: x_proj: n0<BCCOLS -> C0=v (ldc BCCOLS); else dt fold:
//        C1[r*32+head] = softplus(v + bias[head]) for head<32.
#define BM_T    256
#define STG64   49152                   // stage bytes: A 32KB + B 16KB
#define SMEM64  (3 * STG64)             // 144KB dynamic
template<int EPI, int SUP>
__global__ __launch_bounds__(256, 1)
void mma_gemm(const __nv_bfloat16* __restrict__ A, const __nv_bfloat16* __restrict__ W,
              float* __restrict__ C0, float* __restrict__ C1,
              const float* __restrict__ bias,
              int N, int K3, int nbN, int mblocks)
{
    extern __shared__ __align__(128) char sm[];    // 3 * 48KB
    const uint32_t sb = smem_u32(sm);
    const int tid  = threadIdx.x;
    const int lane = tid & 31, wid = tid >> 5;
    const int wm = wid & 3, wn = wid >> 2;         // 4M x 2N warps, 64x64 tiles

    // block swizzle: n-super-panels of width SUP, last panel may be narrower
    const int bid = blockIdx.x;
    const int per_super = mblocks * SUP;
    const int sup = bid / per_super;
    const int nb0 = sup * SUP;
    const int width = (SUP < nbN - nb0) ? SUP : (nbN - nb0);
    const int rem = bid - sup * per_super;
    const int m0 = (rem / width) * BM_T;
    const int n0 = (nb0 + rem % width) * 128;

    // producer indexing: 8 threads per 128B row; rows step by 32
    const int prow = tid >> 3;          // 0..31 (+32i)
    const int pc   = tid & 7;           // 16B chunk 0..7
    const uint32_t pd0 = (uint32_t)(prow * 128 + (((pc ^ (prow & 7))) << 4));
    const __nv_bfloat16* gA = A + (size_t)(m0 + prow) * K3 + pc * 8;
    const __nv_bfloat16* gB = W + (size_t)(n0 + prow) * K3 + pc * 8;

    const int KT = K3 >> 6;             // K3/64

    auto load_stage = [&](int s, int kt) {
        const int koff = kt * 64;
        const uint32_t dbase = sb + (uint32_t)s * STG64;
        // A: 256 rows (8 chunks of 32 rows)
        #pragma unroll
        for (int i = 0; i < 8; i++) {
            const uint32_t d = pd0 + (uint32_t)(i * 32 * 128);
            CP_ASYNC16(dbase + d, gA + (size_t)(i * 32) * K3 + koff);
        }
        // B: 128 rows (4 chunks of 32 rows)
        #pragma unroll
        for (int i = 0; i < 4; i++) {
            const uint32_t d = pd0 + (uint32_t)(i * 32 * 128);
            CP_ASYNC16(dbase + 32768 + d, gB + (size_t)(i * 32) * K3 + koff);
        }
    };

    // consumer: precomputed swizzled LDSM row offsets (ks-invariant part)
    uint32_t pa[4], pb[4];
    #pragma unroll
    for (int mt = 0; mt < 4; mt++) {
        const int row = wm * 64 + mt * 16 + (lane & 15);
        pa[mt] = (uint32_t)(row * 128) + ((uint32_t)(row & 7) << 4);
    }
    #pragma unroll
    for (int nbt = 0; nbt < 4; nbt++) {
        const int row = wn * 64 + nbt * 16 + (lane & 15);
        pb[nbt] = (uint32_t)(row * 128) + ((uint32_t)(row & 7) << 4);
    }
    const uint32_t kcs_base = ((uint32_t)(lane >> 4)) << 4;   // kc = ks*2 + (lane>>4)

    float acc[4][8][4];
    #pragma unroll
    for (int i = 0; i < 4; i++)
        #pragma unroll
        for (int j = 0; j < 8; j++)
            #pragma unroll
            for (int q = 0; q < 4; q++) acc[i][j][q] = 0.0f;

    load_stage(0, 0); CP_COMMIT();
    load_stage(1, 1); CP_COMMIT();

    int scur = 0, spre = 2;        // cycling stage counters (no modulo)
    for (int kt = 0; kt < KT; kt++) {
        CP_WAIT1();
        __syncthreads();
        if (kt + 2 < KT) load_stage(spre, kt + 2);
        CP_COMMIT();                       // empty group ok on tail

        const uint32_t abase = sb + (uint32_t)scur * STG64;
        const uint32_t bbase = abase + 32768;

        #pragma unroll
        for (int ks = 0; ks < 4; ks++) {
            uint32_t aF[4][4], bF[4][4];
            const uint32_t kcs = kcs_base + (uint32_t)(ks << 5);   // (ks*2)<<4
            #pragma unroll
            for (int mt = 0; mt < 4; mt++)
                ldsm4(aF[mt], abase + (pa[mt] ^ kcs));
            #pragma unroll
            for (int nbt = 0; nbt < 4; nbt++)
                ldsm4(bF[nbt], bbase + (pb[nbt] ^ kcs));
            #pragma unroll
            for (int mt = 0; mt < 4; mt++)
                #pragma unroll
                for (int nbt = 0; nbt < 4; nbt++) {
                    mma16816(acc[mt][2 * nbt + 0], aF[mt], bF[nbt][0], bF[nbt][2]);
                    mma16816(acc[mt][2 * nbt + 1], aF[mt], bF[nbt][1], bF[nbt][3]);
                }
        }
        scur = (scur == 2) ? 0 : scur + 1;
        spre = (spre == 2) ? 0 : spre + 1;
    }

    // epilogue
    #pragma unroll
    for (int mt = 0; mt < 4; mt++) {
        #pragma unroll
        for (int nt = 0; nt < 8; nt++) {
            const int r = m0 + wm * 64 + mt * 16 + (lane >> 2);
            const int c = n0 + wn * 64 + nt * 8 + (lane & 3) * 2;
            const float* a4 = acc[mt][nt];
            if (EPI == 0) {
                *(float2*)(C0 + (size_t)r * N + c)       = make_float2(a4[0], a4[1]);
                *(float2*)(C0 + (size_t)(r + 8) * N + c) = make_float2(a4[2], a4[3]);
            } else if (EPI == 1) {
                if (n0 < DINNER) {
                    *(float2*)(C0 + (size_t)r * DINNER + c)       = make_float2(siluf(a4[0]), siluf(a4[1]));
                    *(float2*)(C0 + (size_t)(r + 8) * DINNER + c) = make_float2(siluf(a4[2]), siluf(a4[3]));
                } else {
                    const int cc = c - DINNER;
                    *(float2*)(C1 + (size_t)r * DINNER + cc)       = make_float2(a4[0], a4[1]);
                    *(float2*)(C1 + (size_t)(r + 8) * DINNER + cc) = make_float2(a4[2], a4[3]);
                }
            } else { // EPI == 2
                if (n0 < BCCOLS) {
                    *(float2*)(C0 + (size_t)r * BCCOLS + c)       = make_float2(a4[0], a4[1]);
                    *(float2*)(C0 + (size_t)(r + 8) * BCCOLS + c) = make_float2(a4[2], a4[3]);
                } else {
                    const int head = c - BCCOLS;
                    if (head < NHEADS) {
                        const float b0 = bias[head];
                        C1[(size_t)r * NHEADS + head]       = softplusf(a4[0] + b0);
                        C1[(size_t)(r + 8) * NHEADS + head] = softplusf(a4[2] + b0);
                    }
                    if (head + 1 < NHEADS) {
                        const float b1 = bias[head + 1];
                        C1[(size_t)r * NHEADS + head + 1]       = softplusf(a4[1] + b1);
                        C1[(size_t)(r + 8) * NHEADS + head + 1] = softplusf(a4[3] + b1);
                    }
                }
            }
        }
    }
}

// ============== fp32 -> bf16 hi/lo split, K' = 3K ==============
// A-pattern: [hi | lo | hi]   W-pattern: [hi | hi | lo]
template<bool APAT, bool REMAP>
__global__ __launch_bounds__(256)
void conv3_kernel(const float* __restrict__ src, __nv_bfloat16* __restrict__ dst, int K)
{
    const int c4 = (blockIdx.x * 256 + threadIdx.x) * 4;
    const int row = blockIdx.y;
    const int srow = REMAP ? ((row >> 9) * XPROJ_ROWSTRIDE + (row & 511)) : row;
    float4 v = *(const float4*)(src + (size_t)srow * K + c4);
    __nv_bfloat16 h0 = __float2bfloat16(v.x), h1 = __float2bfloat16(v.y);
    __nv_bfloat16 h2 = __float2bfloat16(v.z), h3 = __float2bfloat16(v.w);
    __nv_bfloat16 l0 = __float2bfloat16(v.x - __bfloat162float(h0));
    __nv_bfloat16 l1 = __float2bfloat16(v.y - __bfloat162float(h1));
    __nv_bfloat16 l2 = __float2bfloat16(v.z - __bfloat162float(h2));
    __nv_bfloat16 l3 = __float2bfloat16(v.w - __bfloat162float(h3));
    __nv_bfloat162 hA = {h0, h1}, hB = {h2, h3};
    __nv_bfloat162 lA = {l0, l1}, lB = {l2, l3};
    __nv_bfloat162* d0 = (__nv_bfloat162*)(dst + (size_t)row * 3 * K + c4);
    __nv_bfloat162* d1 = (__nv_bfloat162*)(dst + (size_t)row * 3 * K + K + c4);
    __nv_bfloat162* d2 = (__nv_bfloat162*)(dst + (size_t)row * 3 * K + 2 * K + c4);
    d0[0] = hA; d0[1] = hB;
    if (APAT) { d1[0] = lA; d1[1] = lB; d2[0] = hA; d2[1] = hB; }
    else      { d1[0] = hA; d1[1] = hB; d2[0] = lA; d2[1] = lB; }
}

// dtw rows appended to g_w3 at rows [BCCOLS, BCCOLS+128): W-pattern, zero pad
__global__ __launch_bounds__(256)
void convdt_kernel(const float* __restrict__ dtw, __nv_bfloat16* __restrict__ dst)
{
    const int c4 = (blockIdx.x * 256 + threadIdx.x) * 4;
    const int r = blockIdx.y;
    __nv_bfloat16* drow = dst + (size_t)(BCCOLS + r) * 3 * DINNER;
    __nv_bfloat162 hA = {(__nv_bfloat16)0.f, (__nv_bfloat16)0.f}, hB = hA, lA = hA, lB = hA;
    if (r < NHEADS) {
        float4 v = *(const float4*)(dtw + (size_t)r * DINNER + c4);
        __nv_bfloat16 h0 = __float2bfloat16(v.x), h1 = __float2bfloat16(v.y);
        __nv_bfloat16 h2 = __float2bfloat16(v.z), h3 = __float2bfloat16(v.w);
        __nv_bfloat16 l0 = __float2bfloat16(v.x - __bfloat162float(h0));
        __nv_bfloat16 l1 = __float2bfloat16(v.y - __bfloat162float(h1));
        __nv_bfloat16 l2 = __float2bfloat16(v.z - __bfloat162float(h2));
        __nv_bfloat16 l3 = __float2bfloat16(v.w - __bfloat162float(h3));
        hA = {h0, h1}; hB = {h2, h3}; lA = {l0, l1}; lB = {l2, l3};
    }
    __nv_bfloat162* d0 = (__nv_bfloat162*)(drow + c4);
    __nv_bfloat162* d1 = (__nv_bfloat162*)(drow + DINNER + c4);
    __nv_bfloat162* d2 = (__nv_bfloat162*)(drow + 2 * DINNER + c4);
    d0[0] = hA; d0[1] = hB;
    d1[0] = hA; d1[1] = hB;
    d2[0] = lA; d2[1] = lB;
}

// ---------------- per-(token,head): RMS norm + discretization coeffs (R8-proven) ----------------
__global__ __launch_bounds__(128, 8)
void prep_kernel(const float* __restrict__ A_, const float* __restrict__ nBw,
                 const float* __restrict__ nCw)
{
    const int m = blockIdx.x;
    const int h = blockIdx.y;
    const int n = threadIdx.x;
    const int b = m >> 11;
    const int t = m & 2047;

    const float2* row = (const float2*)(g_bc + (size_t)m * BCCOLS + h * 512);
    float2 Bv = row[n];
    float2 Cv = row[128 + n];

    __shared__ float red[3][128];
    red[0][n] = Bv.x * Bv.x + Bv.y * Bv.y;
    red[1][n] = Cv.x * Cv.x + Cv.y * Cv.y;
    red[2][n] = (n < HEADD) ? g_x[(size_t)m * DINNER + h * HEADD + n] : 0.0f;
    __syncthreads();
    for (int s = 64; s > 0; s >>= 1) {
        if (n < s) {
            red[0][n] += red[0][n + s];
            red[1][n] += red[1][n + s];
            red[2][n] += red[2][n + s];
        }
        __syncthreads();
    }
    const float rB = rsqrtf(red[0][0] * (1.0f / 256.0f) + 1e-6f);
    const float rC = rsqrtf(red[1][0] * (1.0f / 256.0f) + 1e-6f);
    const float xsum = red[2][0];

    float2 wB = ((const float2*)nBw)[n];
    float2 wC = ((const float2*)nCw)[n];
    float2 Bc = { Bv.x * rB * wB.x, Bv.y * rB * wB.y };
    float2 Cc = { Cv.x * rC * wC.x, Cv.y * rC * wC.y };

    const float dt = g_dt[(size_t)m * NHEADS + h];
    float2 Av = ((const float2*)A_)[h * NSTATE + n];
    const float hdt = 0.5f * dt;
    const float ztr = Av.x * hdt, zti = Av.y * hdt;
    const float dr = 1.0f - ztr, di = -zti;
    const float inv = 1.0f / (dr * dr + di * di);
    const float nr = 1.0f + ztr, ni = zti;
    float2 abar = { (nr * dr + ni * di) * inv, (ni * dr - nr * di) * inv };

    const float s = dt * xsum;
    const float pr = s * dr * inv, pi = -s * di * inv;
    float2 uin = { Bc.x * pr - Bc.y * pi, Bc.x * pi + Bc.y * pr };

    const size_t base = (((size_t)(b * NHEADS + h)) * SEQL + t) * NSTATE + n;
    g_a[base] = abar;
    g_u[base] = uin;
    g_c[base] = Cc;
}

// ---------------- scan (R8-proven): 256 CTAs = 64 (b,h) x 4 n-quarters, 1 warp each ----------------
__global__ __launch_bounds__(32, 8)
void scan_kernel()
{
    const int bh = blockIdx.x >> 2;
    const int q  = blockIdx.x & 3;
    const int b = bh >> 5, h = bh & 31;
    const int lane = threadIdx.x;

    const size_t base = ((size_t)bh * SEQL) * NSTATE + q * 32 + lane;
    float hr = 0.0f, hi = 0.0f;

    __shared__ float rbuf[32][33];

    for (int t0 = 0; t0 < SEQL; t0 += 32) {
        #pragma unroll 8
        for (int tt = 0; tt < 32; tt++) {
            size_t idx = base + (size_t)(t0 + tt) * NSTATE;
            float2 a = g_a[idx];
            float2 u = g_u[idx];
            float2 c = g_c[idx];
            float nhr = fmaf(a.x, hr, fmaf(-a.y, hi, u.x));
            float nhi = fmaf(a.x, hi, fmaf( a.y, hr, u.y));
            hr = nhr; hi = nhi;
            rbuf[tt][lane] = c.x * hr - c.y * hi;
        }
        __syncwarp();
        float p = 0.0f;
        #pragma unroll
        for (int i = 0; i < 32; i++) p += rbuf[lane][i];
        g_yp[((size_t)(b * SEQL + t0 + lane) * NHEADS + h) * 4 + q] = p;
        __syncwarp();
    }
}

// ---------------- gate: yA = split( x * (y_red + D) * silu(z) ) ----------------
__global__ __launch_bounds__(256)
void ymul_kernel(const float* __restrict__ Dv)
{
    const int i4 = (blockIdx.x * 256 + threadIdx.x) * 4;
    const int m = i4 >> 11;
    const int d = i4 & 2047;
    const int h = d >> 6;
    float4 p = *(const float4*)&g_yp[((size_t)m * NHEADS + h) * 4];
    const float scale = (p.x + p.y + p.z + p.w) + Dv[h];
    float4 xv = *(const float4*)&g_x[(size_t)m * DINNER + d];
    float4 zv = *(const float4*)&g_z[(size_t)m * DINNER + d];
    float y0 = xv.x * scale * siluf(zv.x);
    float y1 = xv.y * scale * siluf(zv.y);
    float y2 = xv.z * scale * siluf(zv.z);
    float y3 = xv.w * scale * siluf(zv.w);
    split_store3(g_yA, (size_t)m * (3 * DINNER) + d,     DINNER, y0, y1);
    split_store3(g_yA, (size_t)m * (3 * DINNER) + d + 2, DINNER, y2, y3);
}

// ---------------- launch ----------------
extern "C" void kernel_launch(void* const* d_in, const int* in_sizes, int n_in,
                              void* d_out, int out_size)
{
    const float* u    = (const float*)d_in[0];
    const float* in_w = (const float*)d_in[1];
    const float* dtw  = (const float*)d_in[2];
    const float* dtb  = (const float*)d_in[3];
    const float* xpw  = (const float*)d_in[4];
    const float* Amat = (const float*)d_in[5];
    const float* Dvec = (const float*)d_in[6];
    const float* nBw  = (const float*)d_in[7];
    const float* nCw  = (const float*)d_in[8];
    const float* outw = (const float*)d_in[9];
    float* out        = (float*)d_out;

    void *px, *pz, *pbc, *pdt;
    void *puA, *pw1, *pxA, *pw3, *pyA, *pw4;
    cudaGetSymbolAddress(&px,  g_x);
    cudaGetSymbolAddress(&pz,  g_z);
    cudaGetSymbolAddress(&pbc, g_bc);
    cudaGetSymbolAddress(&pdt, g_dt);
    cudaGetSymbolAddress(&puA, g_uA);
    cudaGetSymbolAddress(&pw1, g_w1);
    cudaGetSymbolAddress(&pxA, g_xA);
    cudaGetSymbolAddress(&pw3, g_w3);
    cudaGetSymbolAddress(&pyA, g_yA);
    cudaGetSymbolAddress(&pw4, g_w4);

    cudaFuncSetAttribute(mma_gemm<1, 8>,  cudaFuncAttributeMaxDynamicSharedMemorySize, SMEM64);
    cudaFuncSetAttribute(mma_gemm<2, 16>, cudaFuncAttributeMaxDynamicSharedMemorySize, SMEM64);
    cudaFuncSetAttribute(mma_gemm<0, 8>,  cudaFuncAttributeMaxDynamicSharedMemorySize, SMEM64);

    // idx 0: conv w3 (biggest weight conversion)
    conv3_kernel<false, true ><<<dim3(DINNER/1024, BCCOLS),   256>>>(xpw, (__nv_bfloat16*)pw3, DINNER);
    // idx 1: conv w1
    conv3_kernel<false, false><<<dim3(DMODEL/1024, 2*DINNER), 256>>>(in_w, (__nv_bfloat16*)pw1, DMODEL);
    // idx 2: conv uA
    conv3_kernel<true,  false><<<dim3(DMODEL/1024, MTOK),     256>>>(u,    (__nv_bfloat16*)puA, DMODEL);
    // idx 3 (ncu profiles this): GEMM1 in_proj + silu/split (M=4096,N=4096,K3=3072)
    mma_gemm<1, 8><<<(MTOK/BM_T) * 32, 256, SMEM64>>>(
        (const __nv_bfloat16*)puA, (const __nv_bfloat16*)pw1,
        (float*)px, (float*)pz, nullptr, 2*DINNER, 3*DMODEL, 32, MTOK/BM_T);
    // idx 4: dtw fold rows for GEMM3
    convdt_kernel<<<dim3(DINNER/1024, 128), 256>>>(dtw, (__nv_bfloat16*)pw3);
    // idx 5: conv w4
    conv3_kernel<false, false><<<dim3(DINNER/1024, DMODEL),   256>>>(outw, (__nv_bfloat16*)pw4, DINNER);
    // idx 6: conv xA
    conv3_kernel<true,  false><<<dim3(DINNER/1024, MTOK),     256>>>((const float*)px, (__nv_bfloat16*)pxA, DINNER);
    // idx 7: GEMM3 x_proj + folded dt (M=4096, N=16512, K3=6144)
    mma_gemm<2, 16><<<(MTOK/BM_T) * (NTOT3/128), 256, SMEM64>>>(
        (const __nv_bfloat16*)pxA, (const __nv_bfloat16*)pw3,
        (float*)pbc, (float*)pdt, dtb, BCCOLS, 3*DINNER, NTOT3/128, MTOK/BM_T);
    // idx 8: prep (full coefficient precompute, R8-proven)
    prep_kernel<<<dim3(MTOK, NHEADS), 128>>>(Amat, nBw, nCw);
    // idx 9: scan (R8-proven)
    scan_kernel<<<BATCH * NHEADS * 4, 32>>>();
    // idx 10: gate (emits bf16 split yA directly)
    ymul_kernel<<<(MTOK * DINNER) / 1024, 256>>>(Dvec);
    // idx 11: GEMM4 out_proj (M=4096, N=1024, K3=6144)
    mma_gemm<0, 8><<<(MTOK/BM_T) * 8, 256, SMEM64>>>(
        (const __nv_bfloat16*)pyA, (const __nv_bfloat16*)pw4,
        out, nullptr, nullptr, DMODEL, 3*DINNER, 8, MTOK/BM_T);

    (void)in_sizes; (void)n_in; (void)out_size;
}

// round 14
// speedup vs baseline: 1.0604x; 1.0604x over previous
#include <cuda_runtime.h>
#include <cuda_bf16.h>
#include <cstdint>
#include <math.h>

// ---------------- problem constants ----------------
#define BATCH   2
#define SEQL    2048
#define MTOK    (BATCH*SEQL)      // 4096
#define DMODEL  1024
#define DINNER  2048
#define NHEADS  32
#define HEADD   64
#define NSTATE  128
#define BCCOLS  16384             // 32 heads * 512 used cols
#define NTOT3   (BCCOLS + 128)    // GEMM3 N incl. folded dt block
#define XPROJ_ROWSTRIDE 513       // x_proj_w has 513 rows per head; last unused

// ---------------- fp32 scratch ----------------
__device__ float  g_x  [(size_t)MTOK*DINNER];     // silu(x)
__device__ float  g_z  [(size_t)MTOK*DINNER];     // raw z
__device__ float  g_dt [(size_t)MTOK*NHEADS];     // softplus(dt)  (folded into GEMM3)
__device__ float  g_bc [(size_t)MTOK*BCCOLS];     // raw BC (per-head 512 cols)
__device__ float2 g_a  [(size_t)BATCH*NHEADS*SEQL*NSTATE]; // abar
__device__ float2 g_u  [(size_t)BATCH*NHEADS*SEQL*NSTATE]; // u_in
__device__ float2 g_c  [(size_t)BATCH*NHEADS*SEQL*NSTATE]; // Cc
__device__ float  g_yp [(size_t)MTOK*NHEADS*4];   // 4-way partial y_red

// ---------------- bf16 hi/lo-split operand scratch (K' = 3K) ----------------
__device__ __nv_bfloat16 g_uA [(size_t)MTOK * 3*DMODEL];    // A' for GEMM1
__device__ __nv_bfloat16 g_w1 [(size_t)(2*DINNER) * 3*DMODEL];
__device__ __nv_bfloat16 g_xA [(size_t)MTOK * 3*DINNER];    // A' for GEMM3
__device__ __nv_bfloat16 g_w3 [(size_t)NTOT3 * 3*DINNER];   // remapped x_proj_w + dtw fold
__device__ __nv_bfloat16 g_yA [(size_t)MTOK * 3*DINNER];    // A' for GEMM4 (ymul-fused)
__device__ __nv_bfloat16 g_w4 [(size_t)DMODEL * 3*DINNER];

// ---------------- helpers ----------------
__device__ __forceinline__ float siluf(float v) { return v / (1.0f + expf(-v)); }
__device__ __forceinline__ float softplusf(float v) { return (v > 20.0f) ? v : log1pf(expf(v)); }

__device__ __forceinline__ uint32_t smem_u32(const void* p) {
    uint32_t a;
    asm("{ .reg .u64 t; cvta.to.shared.u64 t, %1; cvt.u32.u64 %0, t; }" : "=r"(a) : "l"(p));
    return a;
}

__device__ __forceinline__ void ldsm4(uint32_t* r, uint32_t addr) {
    asm volatile("ldmatrix.sync.aligned.m8n8.x4.shared.b16 {%0,%1,%2,%3}, [%4];"
        : "=r"(r[0]), "=r"(r[1]), "=r"(r[2]), "=r"(r[3]) : "r"(addr));
}

__device__ __forceinline__ void mma16816(float* d, const uint32_t* a, uint32_t b0, uint32_t b1) {
    asm volatile("mma.sync.aligned.m16n8k16.row.col.f32.bf16.bf16.f32 "
        "{%0,%1,%2,%3}, {%4,%5,%6,%7}, {%8,%9}, {%0,%1,%2,%3};"
        : "+f"(d[0]), "+f"(d[1]), "+f"(d[2]), "+f"(d[3])
        : "r"(a[0]), "r"(a[1]), "r"(a[2]), "r"(a[3]), "r"(b0), "r"(b1));
}

#define CP_ASYNC16(dst, src) \
    asm volatile("cp.async.cg.shared.global [%0], [%1], 16;" :: "r"(dst), "l"(src) : "memory")
#define CP_COMMIT() asm volatile("cp.async.commit_group;" ::: "memory")
#define CP_WAIT1()  asm volatile("cp.async.wait_group 1;" ::: "memory")

__device__ __forceinline__ void split_store3(__nv_bfloat16* base, size_t off, size_t seg,
                                             float v0, float v1) {
    __nv_bfloat16 h0 = __float2bfloat16(v0), h1 = __float2bfloat16(v1);
    __nv_bfloat16 l0 = __float2bfloat16(v0 - __bfloat162float(h0));
    __nv_bfloat16 l1 = __float2bfloat16(v1 - __bfloat162float(h1));
    __nv_bfloat162 hh = {h0, h1}, ll = {l0, l1};
    *(__nv_bfloat162*)(base + off)           = hh;   // hi
    *(__nv_bfloat162*)(base + off + seg)     = ll;   // lo
    *(__nv_bfloat162*)(base + off + 2 * seg) = hh;   // hi  (A-pattern [hi|lo|hi])
}

// ======= HMMA bf16 GEMM: BM=BN=128, BK=64, 128 thr (4 warps, 2Mx2N, 64x64 tiles) =======
// 3 stages x 32KB (96KB dyn smem) -> 2 CTAs/SM (192KB): keeps R12's cross-CTA overlap
// AND R13's 4:1 MMA:LDSM ratio (8 LDSM -> 32 MMA per k16 sub-step per warp).
// fp32 accumulate (acc 128 regs/thread; ~200 total, no spill at 2x128 thr).
// Swizzle: 128B rows, chunk c ^ (row&7); LDSM addr = (row*128 + ((row&7)<<4)) ^ kcs.
// EPI 0: plain fp32 store (ldc = N).
// EPI 1: in_proj: n0<DINNER -> C0=silu(v); else C1=v.
// EPI 2: x_proj: n0<BCCOLS -> C0=v (ldc BCCOLS); else dt fold:
//        C1[r*32+head] = softplus(v + bias[head]) for head<32.
#define STG64   32768                   // stage bytes: A 16KB + B 16KB
#define SMEM64  (3 * STG64)             // 96KB dynamic
template<int EPI, int SUP>
__global__ __launch_bounds__(128, 2)
void mma_gemm(const __nv_bfloat16* __restrict__ A, const __nv_bfloat16* __restrict__ W,
              float* __restrict__ C0, float* __restrict__ C1,
              const float* __restrict__ bias,
              int N, int K3, int nbN, int mblocks)
{
    extern __shared__ __align__(128) char sm[];    // 3 * 32KB
    const uint32_t sb = smem_u32(sm);
    const int tid  = threadIdx.x;
    const int lane = tid & 31, wid = tid >> 5;
    const int wm = wid & 1, wn = wid >> 1;         // 2M x 2N warps, 64x64 tiles

    // block swizzle: n-super-panels of width SUP, last panel may be narrower
    const int bid = blockIdx.x;
    const int per_super = mblocks * SUP;
    const int sup = bid / per_super;
    const int nb0 = sup * SUP;
    const int width = (SUP < nbN - nb0) ? SUP : (nbN - nb0);
    const int rem = bid - sup * per_super;
    const int m0 = (rem / width) * 128;
    const int n0 = (nb0 + rem % width) * 128;

    // producer indexing: 8 threads per 128B row; 128 threads cover 16 rows/pass
    const int prow = tid >> 3;          // 0..15 (+16i)
    const int pc   = tid & 7;           // 16B chunk 0..7
    const uint32_t pd0 = (uint32_t)(prow * 128 + (((pc ^ (prow & 7))) << 4));
    const __nv_bfloat16* gA = A + (size_t)(m0 + prow) * K3 + pc * 8;
    const __nv_bfloat16* gB = W + (size_t)(n0 + prow) * K3 + pc * 8;

    const int KT = K3 >> 6;             // K3/64

    auto load_stage = [&](int s, int kt) {
        const int koff = kt * 64;
        const uint32_t dbase = sb + (uint32_t)s * STG64;
        #pragma unroll
        for (int i = 0; i < 8; i++) {
            const uint32_t d = pd0 + (uint32_t)(i * 16 * 128);   // rows step by 16
            CP_ASYNC16(dbase + d,         gA + (size_t)(i * 16) * K3 + koff);
            CP_ASYNC16(dbase + 16384 + d, gB + (size_t)(i * 16) * K3 + koff);
        }
    };

    // consumer: precomputed swizzled LDSM row offsets (ks-invariant part)
    uint32_t pa[4], pb[4];
    #pragma unroll
    for (int mt = 0; mt < 4; mt++) {
        const int row = wm * 64 + mt * 16 + (lane & 15);
        pa[mt] = (uint32_t)(row * 128) + ((uint32_t)(row & 7) << 4);
    }
    #pragma unroll
    for (int nbt = 0; nbt < 4; nbt++) {
        const int row = wn * 64 + nbt * 16 + (lane & 15);
        pb[nbt] = (uint32_t)(row * 128) + ((uint32_t)(row & 7) << 4);
    }
    const uint32_t kcs_base = ((uint32_t)(lane >> 4)) << 4;   // kc = ks*2 + (lane>>4)

    float acc[4][8][4];
    #pragma unroll
    for (int i = 0; i < 4; i++)
        #pragma unroll
        for (int j = 0; j < 8; j++)
            #pragma unroll
            for (int q = 0; q < 4; q++) acc[i][j][q] = 0.0f;

    load_stage(0, 0); CP_COMMIT();
    load_stage(1, 1); CP_COMMIT();

    int scur = 0, spre = 2;        // cycling stage counters (no modulo)
    for (int kt = 0; kt < KT; kt++) {
        CP_WAIT1();
        __syncthreads();
        if (kt + 2 < KT) load_stage(spre, kt + 2);
        CP_COMMIT();                       // empty group ok on tail

        const uint32_t abase = sb + (uint32_t)scur * STG64;
        const uint32_t bbase = abase + 16384;

        #pragma unroll
        for (int ks = 0; ks < 4; ks++) {
            uint32_t aF[4][4], bF[4][4];
            const uint32_t kcs = kcs_base + (uint32_t)(ks << 5);   // (ks*2)<<4
            #pragma unroll
            for (int mt = 0; mt < 4; mt++)
                ldsm4(aF[mt], abase + (pa[mt] ^ kcs));
            #pragma unroll
            for (int nbt = 0; nbt < 4; nbt++)
                ldsm4(bF[nbt], bbase + (pb[nbt] ^ kcs));
            #pragma unroll
            for (int mt = 0; mt < 4; mt++)
                #pragma unroll
                for (int nbt = 0; nbt < 4; nbt++) {
                    mma16816(acc[mt][2 * nbt + 0], aF[mt], bF[nbt][0], bF[nbt][2]);
                    mma16816(acc[mt][2 * nbt + 1], aF[mt], bF[nbt][1], bF[nbt][3]);
                }
        }
        scur = (scur == 2) ? 0 : scur + 1;
        spre = (spre == 2) ? 0 : spre + 1;
    }

    // epilogue
    #pragma unroll
    for (int mt = 0; mt < 4; mt++) {
        #pragma unroll
        for (int nt = 0; nt < 8; nt++) {
            const int r = m0 + wm * 64 + mt * 16 + (lane >> 2);
            const int c = n0 + wn * 64 + nt * 8 + (lane & 3) * 2;
            const float* a4 = acc[mt][nt];
            if (EPI == 0) {
                *(float2*)(C0 + (size_t)r * N + c)       = make_float2(a4[0], a4[1]);
                *(float2*)(C0 + (size_t)(r + 8) * N + c) = make_float2(a4[2], a4[3]);
            } else if (EPI == 1) {
                if (n0 < DINNER) {
                    *(float2*)(C0 + (size_t)r * DINNER + c)       = make_float2(siluf(a4[0]), siluf(a4[1]));
                    *(float2*)(C0 + (size_t)(r + 8) * DINNER + c) = make_float2(siluf(a4[2]), siluf(a4[3]));
                } else {
                    const int cc = c - DINNER;
                    *(float2*)(C1 + (size_t)r * DINNER + cc)       = make_float2(a4[0], a4[1]);
                    *(float2*)(C1 + (size_t)(r + 8) * DINNER + cc) = make_float2(a4[2], a4[3]);
                }
            } else { // EPI == 2
                if (n0 < BCCOLS) {
                    *(float2*)(C0 + (size_t)r * BCCOLS + c)       = make_float2(a4[0], a4[1]);
                    *(float2*)(C0 + (size_t)(r + 8) * BCCOLS + c) = make_float2(a4[2], a4[3]);
                } else {
                    const int head = c - BCCOLS;
                    if (head < NHEADS) {
                        const float b0 = bias[head];
                        C1[(size_t)r * NHEADS + head]       = softplusf(a4[0] + b0);
                        C1[(size_t)(r + 8) * NHEADS + head] = softplusf(a4[2] + b0);
                    }
                    if (head + 1 < NHEADS) {
                        const float b1 = bias[head + 1];
                        C1[(size_t)r * NHEADS + head + 1]       = softplusf(a4[1] + b1);
                        C1[(size_t)(r + 8) * NHEADS + head + 1] = softplusf(a4[3] + b1);
                    }
                }
            }
        }
    }
}

// ============== fp32 -> bf16 hi/lo split, K' = 3K ==============
// A-pattern: [hi | lo | hi]   W-pattern: [hi | hi | lo]
template<bool APAT, bool REMAP>
__global__ __launch_bounds__(256)
void conv3_kernel(const float* __restrict__ src, __nv_bfloat16* __restrict__ dst, int K)
{
    const int c4 = (blockIdx.x * 256 + threadIdx.x) * 4;
    const int row = blockIdx.y;
    const int srow = REMAP ? ((row >> 9) * XPROJ_ROWSTRIDE + (row & 511)) : row;
    float4 v = *(const float4*)(src + (size_t)srow * K + c4);
    __nv_bfloat16 h0 = __float2bfloat16(v.x), h1 = __float2bfloat16(v.y);
    __nv_bfloat16 h2 = __float2bfloat16(v.z), h3 = __float2bfloat16(v.w);
    __nv_bfloat16 l0 = __float2bfloat16(v.x - __bfloat162float(h0));
    __nv_bfloat16 l1 = __float2bfloat16(v.y - __bfloat162float(h1));
    __nv_bfloat16 l2 = __float2bfloat16(v.z - __bfloat162float(h2));
    __nv_bfloat16 l3 = __float2bfloat16(v.w - __bfloat162float(h3));
    __nv_bfloat162 hA = {h0, h1}, hB = {h2, h3};
    __nv_bfloat162 lA = {l0, l1}, lB = {l2, l3};
    __nv_bfloat162* d0 = (__nv_bfloat162*)(dst + (size_t)row * 3 * K + c4);
    __nv_bfloat162* d1 = (__nv_bfloat162*)(dst + (size_t)row * 3 * K + K + c4);
    __nv_bfloat162* d2 = (__nv_bfloat162*)(dst + (size_t)row * 3 * K + 2 * K + c4);
    d0[0] = hA; d0[1] = hB;
    if (APAT) { d1[0] = lA; d1[1] = lB; d2[0] = hA; d2[1] = hB; }
    else      { d1[0] = hA; d1[1] = hB; d2[0] = lA; d2[1] = lB; }
}

// dtw rows appended to g_w3 at rows [BCCOLS, BCCOLS+128): W-pattern, zero pad
__global__ __launch_bounds__(256)
void convdt_kernel(const float* __restrict__ dtw, __nv_bfloat16* __restrict__ dst)
{
    const int c4 = (blockIdx.x * 256 + threadIdx.x) * 4;
    const int r = blockIdx.y;
    __nv_bfloat16* drow = dst + (size_t)(BCCOLS + r) * 3 * DINNER;
    __nv_bfloat162 hA = {(__nv_bfloat16)0.f, (__nv_bfloat16)0.f}, hB = hA, lA = hA, lB = hA;
    if (r < NHEADS) {
        float4 v = *(const float4*)(dtw + (size_t)r * DINNER + c4);
        __nv_bfloat16 h0 = __float2bfloat16(v.x), h1 = __float2bfloat16(v.y);
        __nv_bfloat16 h2 = __float2bfloat16(v.z), h3 = __float2bfloat16(v.w);
        __nv_bfloat16 l0 = __float2bfloat16(v.x - __bfloat162float(h0));
        __nv_bfloat16 l1 = __float2bfloat16(v.y - __bfloat162float(h1));
        __nv_bfloat16 l2 = __float2bfloat16(v.z - __bfloat162float(h2));
        __nv_bfloat16 l3 = __float2bfloat16(v.w - __bfloat162float(h3));
        hA = {h0, h1}; hB = {h2, h3}; lA = {l0, l1}; lB = {l2, l3};
    }
    __nv_bfloat162* d0 = (__nv_bfloat162*)(drow + c4);
    __nv_bfloat162* d1 = (__nv_bfloat162*)(drow + DINNER + c4);
    __nv_bfloat162* d2 = (__nv_bfloat162*)(drow + 2 * DINNER + c4);
    d0[0] = hA; d0[1] = hB;
    d1[0] = hA; d1[1] = hB;
    d2[0] = lA; d2[1] = lB;
}

// ---------------- per-(token,head): RMS norm + discretization coeffs (R8-proven) ----------------
__global__ __launch_bounds__(128, 8)
void prep_kernel(const float* __restrict__ A_, const float* __restrict__ nBw,
                 const float* __restrict__ nCw)
{
    const int m = blockIdx.x;
    const int h = blockIdx.y;
    const int n = threadIdx.x;
    const int b = m >> 11;
    const int t = m & 2047;

    const float2* row = (const float2*)(g_bc + (size_t)m * BCCOLS + h * 512);
    float2 Bv = row[n];
    float2 Cv = row[128 + n];

    __shared__ float red[3][128];
    red[0][n] = Bv.x * Bv.x + Bv.y * Bv.y;
    red[1][n] = Cv.x * Cv.x + Cv.y * Cv.y;
    red[2][n] = (n < HEADD) ? g_x[(size_t)m * DINNER + h * HEADD + n] : 0.0f;
    __syncthreads();
    for (int s = 64; s > 0; s >>= 1) {
        if (n < s) {
            red[0][n] += red[0][n + s];
            red[1][n] += red[1][n + s];
            red[2][n] += red[2][n + s];
        }
        __syncthreads();
    }
    const float rB = rsqrtf(red[0][0] * (1.0f / 256.0f) + 1e-6f);
    const float rC = rsqrtf(red[1][0] * (1.0f / 256.0f) + 1e-6f);
    const float xsum = red[2][0];

    float2 wB = ((const float2*)nBw)[n];
    float2 wC = ((const float2*)nCw)[n];
    float2 Bc = { Bv.x * rB * wB.x, Bv.y * rB * wB.y };
    float2 Cc = { Cv.x * rC * wC.x, Cv.y * rC * wC.y };

    const float dt = g_dt[(size_t)m * NHEADS + h];
    float2 Av = ((const float2*)A_)[h * NSTATE + n];
    const float hdt = 0.5f * dt;
    const float ztr = Av.x * hdt, zti = Av.y * hdt;
    const float dr = 1.0f - ztr, di = -zti;
    const float inv = 1.0f / (dr * dr + di * di);
    const float nr = 1.0f + ztr, ni = zti;
    float2 abar = { (nr * dr + ni * di) * inv, (ni * dr - nr * di) * inv };

    const float s = dt * xsum;
    const float pr = s * dr * inv, pi = -s * di * inv;
    float2 uin = { Bc.x * pr - Bc.y * pi, Bc.x * pi + Bc.y * pr };

    const size_t base = (((size_t)(b * NHEADS + h)) * SEQL + t) * NSTATE + n;
    g_a[base] = abar;
    g_u[base] = uin;
    g_c[base] = Cc;
}

// ---------------- scan (R8-proven): 256 CTAs = 64 (b,h) x 4 n-quarters, 1 warp each ----------------
__global__ __launch_bounds__(32, 8)
void scan_kernel()
{
    const int bh = blockIdx.x >> 2;
    const int q  = blockIdx.x & 3;
    const int b = bh >> 5, h = bh & 31;
    const int lane = threadIdx.x;

    const size_t base = ((size_t)bh * SEQL) * NSTATE + q * 32 + lane;
    float hr = 0.0f, hi = 0.0f;

    __shared__ float rbuf[32][33];

    for (int t0 = 0; t0 < SEQL; t0 += 32) {
        #pragma unroll 8
        for (int tt = 0; tt < 32; tt++) {
            size_t idx = base + (size_t)(t0 + tt) * NSTATE;
            float2 a = g_a[idx];
            float2 u = g_u[idx];
            float2 c = g_c[idx];
            float nhr = fmaf(a.x, hr, fmaf(-a.y, hi, u.x));
            float nhi = fmaf(a.x, hi, fmaf( a.y, hr, u.y));
            hr = nhr; hi = nhi;
            rbuf[tt][lane] = c.x * hr - c.y * hi;
        }
        __syncwarp();
        float p = 0.0f;
        #pragma unroll
        for (int i = 0; i < 32; i++) p += rbuf[lane][i];
        g_yp[((size_t)(b * SEQL + t0 + lane) * NHEADS + h) * 4 + q] = p;
        __syncwarp();
    }
}

// ---------------- gate: yA = split( x * (y_red + D) * silu(z) ) ----------------
__global__ __launch_bounds__(256)
void ymul_kernel(const float* __restrict__ Dv)
{
    const int i4 = (blockIdx.x * 256 + threadIdx.x) * 4;
    const int m = i4 >> 11;
    const int d = i4 & 2047;
    const int h = d >> 6;
    float4 p = *(const float4*)&g_yp[((size_t)m * NHEADS + h) * 4];
    const float scale = (p.x + p.y + p.z + p.w) + Dv[h];
    float4 xv = *(const float4*)&g_x[(size_t)m * DINNER + d];
    float4 zv = *(const float4*)&g_z[(size_t)m * DINNER + d];
    float y0 = xv.x * scale * siluf(zv.x);
    float y1 = xv.y * scale * siluf(zv.y);
    float y2 = xv.z * scale * siluf(zv.z);
    float y3 = xv.w * scale * siluf(zv.w);
    split_store3(g_yA, (size_t)m * (3 * DINNER) + d,     DINNER, y0, y1);
    split_store3(g_yA, (size_t)m * (3 * DINNER) + d + 2, DINNER, y2, y3);
}

// ---------------- launch ----------------
extern "C" void kernel_launch(void* const* d_in, const int* in_sizes, int n_in,
                              void* d_out, int out_size)
{
    const float* u    = (const float*)d_in[0];
    const float* in_w = (const float*)d_in[1];
    const float* dtw  = (const float*)d_in[2];
    const float* dtb  = (const float*)d_in[3];
    const float* xpw  = (const float*)d_in[4];
    const float* Amat = (const float*)d_in[5];
    const float* Dvec = (const float*)d_in[6];
    const float* nBw  = (const float*)d_in[7];
    const float* nCw  = (const float*)d_in[8];
    const float* outw = (const float*)d_in[9];
    float* out        = (float*)d_out;

    void *px, *pz, *pbc, *pdt;
    void *puA, *pw1, *pxA, *pw3, *pyA, *pw4;
    cudaGetSymbolAddress(&px,  g_x);
    cudaGetSymbolAddress(&pz,  g_z);
    cudaGetSymbolAddress(&pbc, g_bc);
    cudaGetSymbolAddress(&pdt, g_dt);
    cudaGetSymbolAddress(&puA, g_uA);
    cudaGetSymbolAddress(&pw1, g_w1);
    cudaGetSymbolAddress(&pxA, g_xA);
    cudaGetSymbolAddress(&pw3, g_w3);
    cudaGetSymbolAddress(&pyA, g_yA);
    cudaGetSymbolAddress(&pw4, g_w4);

    cudaFuncSetAttribute(mma_gemm<1, 8>,  cudaFuncAttributeMaxDynamicSharedMemorySize, SMEM64);
    cudaFuncSetAttribute(mma_gemm<2, 16>, cudaFuncAttributeMaxDynamicSharedMemorySize, SMEM64);
    cudaFuncSetAttribute(mma_gemm<0, 8>,  cudaFuncAttributeMaxDynamicSharedMemorySize, SMEM64);

    // idx 0: conv w3 (biggest weight conversion)
    conv3_kernel<false, true ><<<dim3(DINNER/1024, BCCOLS),   256>>>(xpw, (__nv_bfloat16*)pw3, DINNER);
    // idx 1: conv w1
    conv3_kernel<false, false><<<dim3(DMODEL/1024, 2*DINNER), 256>>>(in_w, (__nv_bfloat16*)pw1, DMODEL);
    // idx 2: conv uA
    conv3_kernel<true,  false><<<dim3(DMODEL/1024, MTOK),     256>>>(u,    (__nv_bfloat16*)puA, DMODEL);
    // idx 3 (ncu profiles this): GEMM1 in_proj + silu/split (M=4096,N=4096,K3=3072)
    mma_gemm<1, 8><<<32 * 32, 128, SMEM64>>>(
        (const __nv_bfloat16*)puA, (const __nv_bfloat16*)pw1,
        (float*)px, (float*)pz, nullptr, 2*DINNER, 3*DMODEL, 32, 32);
    // idx 4: dtw fold rows for GEMM3
    convdt_kernel<<<dim3(DINNER/1024, 128), 256>>>(dtw, (__nv_bfloat16*)pw3);
    // idx 5: conv w4
    conv3_kernel<false, false><<<dim3(DINNER/1024, DMODEL),   256>>>(outw, (__nv_bfloat16*)pw4, DINNER);
    // idx 6: conv xA
    conv3_kernel<true,  false><<<dim3(DINNER/1024, MTOK),     256>>>((const float*)px, (__nv_bfloat16*)pxA, DINNER);
    // idx 7: GEMM3 x_proj + folded dt (M=4096, N=16512, K3=6144)
    mma_gemm<2, 16><<<32 * (NTOT3/128), 128, SMEM64>>>(
        (const __nv_bfloat16*)pxA, (const __nv_bfloat16*)pw3,
        (float*)pbc, (float*)pdt, dtb, BCCOLS, 3*DINNER, NTOT3/128, 32);
    // idx 8: prep (full coefficient precompute, R8-proven)
    prep_kernel<<<dim3(MTOK, NHEADS), 128>>>(Amat, nBw, nCw);
    // idx 9: scan (R8-proven)
    scan_kernel<<<BATCH * NHEADS * 4, 32>>>();
    // idx 10: gate (emits bf16 split yA directly)
    ymul_kernel<<<(MTOK * DINNER) / 1024, 256>>>(Dvec);
    // idx 11: GEMM4 out_proj (M=4096, N=1024, K3=6144)
    mma_gemm<0, 8><<<32 * 8, 128, SMEM64>>>(
        (const __nv_bfloat16*)pyA, (const __nv_bfloat16*)pw4,
        out, nullptr, nullptr, DMODEL, 3*DINNER, 8, 32);

    (void)in_sizes; (void)n_in; (void)out_size;
}

// round 15
// speedup vs baseline: 1.1098x; 1.0466x over previous
#include <cuda_runtime.h>
#include <cuda_bf16.h>
#include <cstdint>
#include <math.h>

// ---------------- problem constants ----------------
#define BATCH   2
#define SEQL    2048
#define MTOK    (BATCH*SEQL)      // 4096
#define DMODEL  1024
#define DINNER  2048
#define NHEADS  32
#define HEADD   64
#define NSTATE  128
#define BCCOLS  16384             // 32 heads * 512 used cols
#define NTOT3   (BCCOLS + 128)    // GEMM3 N incl. folded dt block
#define XPROJ_ROWSTRIDE 513       // x_proj_w has 513 rows per head; last unused

// ---------------- fp32 scratch ----------------
__device__ float  g_x  [(size_t)MTOK*DINNER];     // silu(x)
__device__ float  g_z  [(size_t)MTOK*DINNER];     // raw z
__device__ float  g_dt [(size_t)MTOK*NHEADS];     // softplus(dt)  (folded into GEMM3)
__device__ float  g_bc [(size_t)MTOK*BCCOLS];     // raw BC (per-head 512 cols)
__device__ float2 g_a  [(size_t)BATCH*NHEADS*SEQL*NSTATE]; // abar
__device__ float2 g_u  [(size_t)BATCH*NHEADS*SEQL*NSTATE]; // u_in
__device__ float2 g_c  [(size_t)BATCH*NHEADS*SEQL*NSTATE]; // Cc
__device__ float  g_yp [(size_t)MTOK*NHEADS*4];   // 4-way partial y_red

// ---------------- bf16 hi/lo-split operand scratch (K' = 3K) ----------------
__device__ __nv_bfloat16 g_uA [(size_t)MTOK * 3*DMODEL];    // A' for GEMM1
__device__ __nv_bfloat16 g_w1 [(size_t)(2*DINNER) * 3*DMODEL];
__device__ __nv_bfloat16 g_xA [(size_t)MTOK * 3*DINNER];    // A' for GEMM3
__device__ __nv_bfloat16 g_w3 [(size_t)NTOT3 * 3*DINNER];   // remapped x_proj_w + dtw fold
__device__ __nv_bfloat16 g_yA [(size_t)MTOK * 3*DINNER];    // A' for GEMM4 (ymul-fused)
__device__ __nv_bfloat16 g_w4 [(size_t)DMODEL * 3*DINNER];

// ---------------- helpers ----------------
__device__ __forceinline__ float siluf(float v) { return v / (1.0f + expf(-v)); }
__device__ __forceinline__ float softplusf(float v) { return (v > 20.0f) ? v : log1pf(expf(v)); }

__device__ __forceinline__ uint32_t smem_u32(const void* p) {
    uint32_t a;
    asm("{ .reg .u64 t; cvta.to.shared.u64 t, %1; cvt.u32.u64 %0, t; }" : "=r"(a) : "l"(p));
    return a;
}

__device__ __forceinline__ void ldsm4(uint32_t* r, uint32_t addr) {
    asm volatile("ldmatrix.sync.aligned.m8n8.x4.shared.b16 {%0,%1,%2,%3}, [%4];"
        : "=r"(r[0]), "=r"(r[1]), "=r"(r[2]), "=r"(r[3]) : "r"(addr));
}

__device__ __forceinline__ void mma16816(float* d, const uint32_t* a, uint32_t b0, uint32_t b1) {
    asm volatile("mma.sync.aligned.m16n8k16.row.col.f32.bf16.bf16.f32 "
        "{%0,%1,%2,%3}, {%4,%5,%6,%7}, {%8,%9}, {%0,%1,%2,%3};"
        : "+f"(d[0]), "+f"(d[1]), "+f"(d[2]), "+f"(d[3])
        : "r"(a[0]), "r"(a[1]), "r"(a[2]), "r"(a[3]), "r"(b0), "r"(b1));
}

#define CP_ASYNC16(dst, src) \
    asm volatile("cp.async.cg.shared.global [%0], [%1], 16;" :: "r"(dst), "l"(src) : "memory")
#define CP_COMMIT() asm volatile("cp.async.commit_group;" ::: "memory")
#define CP_WAIT1()  asm volatile("cp.async.wait_group 1;" ::: "memory")

__device__ __forceinline__ void split_store3(__nv_bfloat16* base, size_t off, size_t seg,
                                             float v0, float v1) {
    __nv_bfloat16 h0 = __float2bfloat16(v0), h1 = __float2bfloat16(v1);
    __nv_bfloat16 l0 = __float2bfloat16(v0 - __bfloat162float(h0));
    __nv_bfloat16 l1 = __float2bfloat16(v1 - __bfloat162float(h1));
    __nv_bfloat162 hh = {h0, h1}, ll = {l0, l1};
    *(__nv_bfloat162*)(base + off)           = hh;   // hi
    *(__nv_bfloat162*)(base + off + seg)     = ll;   // lo
    *(__nv_bfloat162*)(base + off + 2 * seg) = hh;   // hi  (A-pattern [hi|lo|hi])
}

// ================= HMMA bf16 GEMM (R12-proven): BK=64, 3 stages x 32KB =================
// BM=BN=128, BK=64 (bf16, 128B rows), 256 threads (8 warps, 4M x 2N), warp tile 32x64
// via m16n8k16, 4 k16 sub-steps per kt. fp32 accumulate. 2 CTAs/SM (192KB smem total).
// Swizzle: chunk c ^ (row&7) on 128B rows; LDSM addr = (row*128 + ((row&7)<<4)) ^ kcs.
// EPI 0: plain fp32 store (ldc = N).
// EPI 1: in_proj: n0<DINNER -> C0=silu(v); else C1=v.
// EPI 2: x_proj: n0<BCCOLS -> C0=v (ldc BCCOLS); else dt fold:
//        C1[r*32+head] = softplus(v + bias[head]) for head<32.
#define STG64   32768                   // stage bytes: A 16KB + B 16KB
#define SMEM64  (3 * STG64)             // 96KB dynamic
template<int EPI, int SUP>
__global__ __launch_bounds__(256, 2)
void mma_gemm(const __nv_bfloat16* __restrict__ A, const __nv_bfloat16* __restrict__ W,
              float* __restrict__ C0, float* __restrict__ C1,
              const float* __restrict__ bias,
              int N, int K3, int nbN, int mblocks)
{
    extern __shared__ __align__(128) char sm[];    // 3 * 32KB
    const uint32_t sb = smem_u32(sm);
    const int tid  = threadIdx.x;
    const int lane = tid & 31, wid = tid >> 5;
    const int wm = wid & 3, wn = wid >> 2;

    // block swizzle: n-super-panels of width SUP, last panel may be narrower
    const int bid = blockIdx.x;
    const int per_super = mblocks * SUP;
    const int sup = bid / per_super;
    const int nb0 = sup * SUP;
    const int width = (SUP < nbN - nb0) ? SUP : (nbN - nb0);
    const int rem = bid - sup * per_super;
    const int m0 = (rem / width) * 128;
    const int n0 = (nb0 + rem % width) * 128;

    // producer indexing: 8 threads per 128B row; rows step by 32
    const int prow = tid >> 3;          // 0..31 (+32i)
    const int pc   = tid & 7;           // 16B chunk 0..7
    const uint32_t pd0 = (uint32_t)(prow * 128 + (((pc ^ (prow & 7))) << 4));
    const __nv_bfloat16* gA = A + (size_t)(m0 + prow) * K3 + pc * 8;
    const __nv_bfloat16* gB = W + (size_t)(n0 + prow) * K3 + pc * 8;

    const int KT = K3 >> 6;             // K3/64

    auto load_stage = [&](int s, int kt) {
        const int koff = kt * 64;
        const uint32_t dbase = sb + (uint32_t)s * STG64;
        #pragma unroll
        for (int i = 0; i < 4; i++) {
            const uint32_t d = pd0 + (uint32_t)(i * 32 * 128);   // rows step by 32
            CP_ASYNC16(dbase + d,         gA + (size_t)(i * 32) * K3 + koff);
            CP_ASYNC16(dbase + 16384 + d, gB + (size_t)(i * 32) * K3 + koff);
        }
    };

    // consumer: precomputed swizzled LDSM row offsets (ks-invariant part)
    uint32_t pa[2], pb[4];
    #pragma unroll
    for (int mt = 0; mt < 2; mt++) {
        const int row = wm * 32 + mt * 16 + (lane & 15);
        pa[mt] = (uint32_t)(row * 128) + ((uint32_t)(row & 7) << 4);
    }
    #pragma unroll
    for (int nbt = 0; nbt < 4; nbt++) {
        const int row = wn * 64 + nbt * 16 + (lane & 15);
        pb[nbt] = (uint32_t)(row * 128) + ((uint32_t)(row & 7) << 4);
    }
    const uint32_t kcs_base = ((uint32_t)(lane >> 4)) << 4;   // kc = ks*2 + (lane>>4)

    float acc[2][8][4];
    #pragma unroll
    for (int i = 0; i < 2; i++)
        #pragma unroll
        for (int j = 0; j < 8; j++)
            #pragma unroll
            for (int q = 0; q < 4; q++) acc[i][j][q] = 0.0f;

    load_stage(0, 0); CP_COMMIT();
    load_stage(1, 1); CP_COMMIT();

    int scur = 0, spre = 2;        // cycling stage counters (no modulo)
    for (int kt = 0; kt < KT; kt++) {
        CP_WAIT1();
        __syncthreads();
        if (kt + 2 < KT) load_stage(spre, kt + 2);
        CP_COMMIT();                       // empty group ok on tail

        const uint32_t abase = sb + (uint32_t)scur * STG64;
        const uint32_t bbase = abase + 16384;

        #pragma unroll
        for (int ks = 0; ks < 4; ks++) {
            uint32_t aF[2][4], bF[4][4];
            const uint32_t kcs = kcs_base + (uint32_t)(ks << 5);   // (ks*2)<<4
            #pragma unroll
            for (int mt = 0; mt < 2; mt++)
                ldsm4(aF[mt], abase + (pa[mt] ^ kcs));
            #pragma unroll
            for (int nbt = 0; nbt < 4; nbt++)
                ldsm4(bF[nbt], bbase + (pb[nbt] ^ kcs));
            #pragma unroll
            for (int mt = 0; mt < 2; mt++)
                #pragma unroll
                for (int nbt = 0; nbt < 4; nbt++) {
                    mma16816(acc[mt][2 * nbt + 0], aF[mt], bF[nbt][0], bF[nbt][2]);
                    mma16816(acc[mt][2 * nbt + 1], aF[mt], bF[nbt][1], bF[nbt][3]);
                }
        }
        scur = (scur == 2) ? 0 : scur + 1;
        spre = (spre == 2) ? 0 : spre + 1;
    }

    // epilogue
    #pragma unroll
    for (int mt = 0; mt < 2; mt++) {
        #pragma unroll
        for (int nt = 0; nt < 8; nt++) {
            const int r = m0 + wm * 32 + mt * 16 + (lane >> 2);
            const int c = n0 + wn * 64 + nt * 8 + (lane & 3) * 2;
            const float* a4 = acc[mt][nt];
            if (EPI == 0) {
                *(float2*)(C0 + (size_t)r * N + c)       = make_float2(a4[0], a4[1]);
                *(float2*)(C0 + (size_t)(r + 8) * N + c) = make_float2(a4[2], a4[3]);
            } else if (EPI == 1) {
                if (n0 < DINNER) {
                    *(float2*)(C0 + (size_t)r * DINNER + c)       = make_float2(siluf(a4[0]), siluf(a4[1]));
                    *(float2*)(C0 + (size_t)(r + 8) * DINNER + c) = make_float2(siluf(a4[2]), siluf(a4[3]));
                } else {
                    const int cc = c - DINNER;
                    *(float2*)(C1 + (size_t)r * DINNER + cc)       = make_float2(a4[0], a4[1]);
                    *(float2*)(C1 + (size_t)(r + 8) * DINNER + cc) = make_float2(a4[2], a4[3]);
                }
            } else { // EPI == 2
                if (n0 < BCCOLS) {
                    *(float2*)(C0 + (size_t)r * BCCOLS + c)       = make_float2(a4[0], a4[1]);
                    *(float2*)(C0 + (size_t)(r + 8) * BCCOLS + c) = make_float2(a4[2], a4[3]);
                } else {
                    const int head = c - BCCOLS;
                    if (head < NHEADS) {
                        const float b0 = bias[head];
                        C1[(size_t)r * NHEADS + head]       = softplusf(a4[0] + b0);
                        C1[(size_t)(r + 8) * NHEADS + head] = softplusf(a4[2] + b0);
                    }
                    if (head + 1 < NHEADS) {
                        const float b1 = bias[head + 1];
                        C1[(size_t)r * NHEADS + head + 1]       = softplusf(a4[1] + b1);
                        C1[(size_t)(r + 8) * NHEADS + head + 1] = softplusf(a4[3] + b1);
                    }
                }
            }
        }
    }
}

// ============== fp32 -> bf16 hi/lo split, K' = 3K ==============
// A-pattern: [hi | lo | hi]   W-pattern: [hi | hi | lo]
template<bool APAT, bool REMAP>
__global__ __launch_bounds__(256)
void conv3_kernel(const float* __restrict__ src, __nv_bfloat16* __restrict__ dst, int K)
{
    const int c4 = (blockIdx.x * 256 + threadIdx.x) * 4;
    const int row = blockIdx.y;
    const int srow = REMAP ? ((row >> 9) * XPROJ_ROWSTRIDE + (row & 511)) : row;
    float4 v = *(const float4*)(src + (size_t)srow * K + c4);
    __nv_bfloat16 h0 = __float2bfloat16(v.x), h1 = __float2bfloat16(v.y);
    __nv_bfloat16 h2 = __float2bfloat16(v.z), h3 = __float2bfloat16(v.w);
    __nv_bfloat16 l0 = __float2bfloat16(v.x - __bfloat162float(h0));
    __nv_bfloat16 l1 = __float2bfloat16(v.y - __bfloat162float(h1));
    __nv_bfloat16 l2 = __float2bfloat16(v.z - __bfloat162float(h2));
    __nv_bfloat16 l3 = __float2bfloat16(v.w - __bfloat162float(h3));
    __nv_bfloat162 hA = {h0, h1}, hB = {h2, h3};
    __nv_bfloat162 lA = {l0, l1}, lB = {l2, l3};
    __nv_bfloat162* d0 = (__nv_bfloat162*)(dst + (size_t)row * 3 * K + c4);
    __nv_bfloat162* d1 = (__nv_bfloat162*)(dst + (size_t)row * 3 * K + K + c4);
    __nv_bfloat162* d2 = (__nv_bfloat162*)(dst + (size_t)row * 3 * K + 2 * K + c4);
    d0[0] = hA; d0[1] = hB;
    if (APAT) { d1[0] = lA; d1[1] = lB; d2[0] = hA; d2[1] = hB; }
    else      { d1[0] = hA; d1[1] = hB; d2[0] = lA; d2[1] = lB; }
}

// dtw rows appended to g_w3 at rows [BCCOLS, BCCOLS+128): W-pattern, zero pad
__global__ __launch_bounds__(256)
void convdt_kernel(const float* __restrict__ dtw, __nv_bfloat16* __restrict__ dst)
{
    const int c4 = (blockIdx.x * 256 + threadIdx.x) * 4;
    const int r = blockIdx.y;
    __nv_bfloat16* drow = dst + (size_t)(BCCOLS + r) * 3 * DINNER;
    __nv_bfloat162 hA = {(__nv_bfloat16)0.f, (__nv_bfloat16)0.f}, hB = hA, lA = hA, lB = hA;
    if (r < NHEADS) {
        float4 v = *(const float4*)(dtw + (size_t)r * DINNER + c4);
        __nv_bfloat16 h0 = __float2bfloat16(v.x), h1 = __float2bfloat16(v.y);
        __nv_bfloat16 h2 = __float2bfloat16(v.z), h3 = __float2bfloat16(v.w);
        __nv_bfloat16 l0 = __float2bfloat16(v.x - __bfloat162float(h0));
        __nv_bfloat16 l1 = __float2bfloat16(v.y - __bfloat162float(h1));
        __nv_bfloat16 l2 = __float2bfloat16(v.z - __bfloat162float(h2));
        __nv_bfloat16 l3 = __float2bfloat16(v.w - __bfloat162float(h3));
        hA = {h0, h1}; hB = {h2, h3}; lA = {l0, l1}; lB = {l2, l3};
    }
    __nv_bfloat162* d0 = (__nv_bfloat162*)(drow + c4);
    __nv_bfloat162* d1 = (__nv_bfloat162*)(drow + DINNER + c4);
    __nv_bfloat162* d2 = (__nv_bfloat162*)(drow + 2 * DINNER + c4);
    d0[0] = hA; d0[1] = hB;
    d1[0] = hA; d1[1] = hB;
    d2[0] = lA; d2[1] = lB;
}

// ---------------- prep: warp per (m,h), shuffle reductions, zero barriers ----------------
// grid (MTOK, NHEADS/4), 128 threads. Lane handles 4 consecutive states.
__global__ __launch_bounds__(128, 8)
void prep_kernel(const float* __restrict__ A_, const float* __restrict__ nBw,
                 const float* __restrict__ nCw)
{
    const int m = blockIdx.x;
    const int h = blockIdx.y * 4 + (threadIdx.x >> 5);
    const int lane = threadIdx.x & 31;
    const int b = m >> 11;
    const int t = m & 2047;

    const float4* bcp = (const float4*)(g_bc + (size_t)m * BCCOLS + h * 512);
    // B: float4 idx [0,64), C: [64,128). Lane loads 2 consecutive float4 of each.
    float4 b0 = bcp[lane * 2],      b1 = bcp[lane * 2 + 1];
    float4 c0 = bcp[64 + lane * 2], c1 = bcp[64 + lane * 2 + 1];

    float sB = b0.x*b0.x + b0.y*b0.y + b0.z*b0.z + b0.w*b0.w
             + b1.x*b1.x + b1.y*b1.y + b1.z*b1.z + b1.w*b1.w;
    float sC = c0.x*c0.x + c0.y*c0.y + c0.z*c0.z + c0.w*c0.w
             + c1.x*c1.x + c1.y*c1.y + c1.z*c1.z + c1.w*c1.w;
    float2 xv = ((const float2*)(g_x + (size_t)m * DINNER + h * HEADD))[lane];
    float sx = xv.x + xv.y;

    #pragma unroll
    for (int off = 16; off; off >>= 1) {
        sB += __shfl_xor_sync(0xFFFFFFFFu, sB, off);
        sC += __shfl_xor_sync(0xFFFFFFFFu, sC, off);
        sx += __shfl_xor_sync(0xFFFFFFFFu, sx, off);
    }

    const float rB = rsqrtf(sB * (1.0f / 256.0f) + 1e-6f);
    const float rC = rsqrtf(sC * (1.0f / 256.0f) + 1e-6f);
    const float dt = g_dt[(size_t)m * NHEADS + h];
    const float hdt = 0.5f * dt;
    const float sdt = dt * sx;

    // per-lane: 4 consecutive states n = 4*lane + j
    const int n0 = lane * 4;
    float2 Bv[4] = { {b0.x, b0.y}, {b0.z, b0.w}, {b1.x, b1.y}, {b1.z, b1.w} };
    float2 Cv[4] = { {c0.x, c0.y}, {c0.z, c0.w}, {c1.x, c1.y}, {c1.z, c1.w} };

    const float4* Avp = (const float4*)((const float2*)A_ + h * NSTATE + n0);
    float4 Av01 = Avp[0], Av23 = Avp[1];
    float2 Av[4] = { {Av01.x, Av01.y}, {Av01.z, Av01.w}, {Av23.x, Av23.y}, {Av23.z, Av23.w} };

    const float4* wBp = (const float4*)((const float2*)nBw + n0);
    const float4* wCp = (const float4*)((const float2*)nCw + n0);
    float4 wB01 = wBp[0], wB23 = wBp[1], wC01 = wCp[0], wC23 = wCp[1];
    float2 wB[4] = { {wB01.x, wB01.y}, {wB01.z, wB01.w}, {wB23.x, wB23.y}, {wB23.z, wB23.w} };
    float2 wC[4] = { {wC01.x, wC01.y}, {wC01.z, wC01.w}, {wC23.x, wC23.y}, {wC23.z, wC23.w} };

    float2 av[4], uv[4], cv[4];
    #pragma unroll
    for (int j = 0; j < 4; j++) {
        const float ztr = Av[j].x * hdt, zti = Av[j].y * hdt;
        const float dr = 1.0f - ztr, di = -zti;
        const float inv = 1.0f / (dr * dr + di * di);
        const float nr = 1.0f + ztr, ni = zti;
        av[j].x = (nr * dr + ni * di) * inv;
        av[j].y = (ni * dr - nr * di) * inv;
        const float pr = sdt * dr * inv, pi = -sdt * di * inv;
        const float Bcx = Bv[j].x * rB * wB[j].x, Bcy = Bv[j].y * rB * wB[j].y;
        uv[j].x = Bcx * pr - Bcy * pi;
        uv[j].y = Bcx * pi + Bcy * pr;
        cv[j].x = Cv[j].x * rC * wC[j].x;
        cv[j].y = Cv[j].y * rC * wC[j].y;
    }

    const size_t base = (((size_t)(b * NHEADS + h)) * SEQL + t) * NSTATE + n0;
    float4* ap = (float4*)&g_a[base];
    float4* up = (float4*)&g_u[base];
    float4* cp = (float4*)&g_c[base];
    ap[0] = make_float4(av[0].x, av[0].y, av[1].x, av[1].y);
    ap[1] = make_float4(av[2].x, av[2].y, av[3].x, av[3].y);
    up[0] = make_float4(uv[0].x, uv[0].y, uv[1].x, uv[1].y);
    up[1] = make_float4(uv[2].x, uv[2].y, uv[3].x, uv[3].y);
    cp[0] = make_float4(cv[0].x, cv[0].y, cv[1].x, cv[1].y);
    cp[1] = make_float4(cv[2].x, cv[2].y, cv[3].x, cv[3].y);
}

// ---------------- scan (R8-proven): 256 CTAs = 64 (b,h) x 4 n-quarters, 1 warp each ----------------
__global__ __launch_bounds__(32, 8)
void scan_kernel()
{
    const int bh = blockIdx.x >> 2;
    const int q  = blockIdx.x & 3;
    const int b = bh >> 5, h = bh & 31;
    const int lane = threadIdx.x;

    const size_t base = ((size_t)bh * SEQL) * NSTATE + q * 32 + lane;
    float hr = 0.0f, hi = 0.0f;

    __shared__ float rbuf[32][33];

    for (int t0 = 0; t0 < SEQL; t0 += 32) {
        #pragma unroll 8
        for (int tt = 0; tt < 32; tt++) {
            size_t idx = base + (size_t)(t0 + tt) * NSTATE;
            float2 a = g_a[idx];
            float2 u = g_u[idx];
            float2 c = g_c[idx];
            float nhr = fmaf(a.x, hr, fmaf(-a.y, hi, u.x));
            float nhi = fmaf(a.x, hi, fmaf( a.y, hr, u.y));
            hr = nhr; hi = nhi;
            rbuf[tt][lane] = c.x * hr - c.y * hi;
        }
        __syncwarp();
        float p = 0.0f;
        #pragma unroll
        for (int i = 0; i < 32; i++) p += rbuf[lane][i];
        g_yp[((size_t)(b * SEQL + t0 + lane) * NHEADS + h) * 4 + q] = p;
        __syncwarp();
    }
}

// ---------------- gate: yA = split( x * (y_red + D) * silu(z) ) ----------------
__global__ __launch_bounds__(256)
void ymul_kernel(const float* __restrict__ Dv)
{
    const int i4 = (blockIdx.x * 256 + threadIdx.x) * 4;
    const int m = i4 >> 11;
    const int d = i4 & 2047;
    const int h = d >> 6;
    float4 p = *(const float4*)&g_yp[((size_t)m * NHEADS + h) * 4];
    const float scale = (p.x + p.y + p.z + p.w) + Dv[h];
    float4 xv = *(const float4*)&g_x[(size_t)m * DINNER + d];
    float4 zv = *(const float4*)&g_z[(size_t)m * DINNER + d];
    float y0 = xv.x * scale * siluf(zv.x);
    float y1 = xv.y * scale * siluf(zv.y);
    float y2 = xv.z * scale * siluf(zv.z);
    float y3 = xv.w * scale * siluf(zv.w);
    split_store3(g_yA, (size_t)m * (3 * DINNER) + d,     DINNER, y0, y1);
    split_store3(g_yA, (size_t)m * (3 * DINNER) + d + 2, DINNER, y2, y3);
}

// ---------------- launch ----------------
extern "C" void kernel_launch(void* const* d_in, const int* in_sizes, int n_in,
                              void* d_out, int out_size)
{
    const float* u    = (const float*)d_in[0];
    const float* in_w = (const float*)d_in[1];
    const float* dtw  = (const float*)d_in[2];
    const float* dtb  = (const float*)d_in[3];
    const float* xpw  = (const float*)d_in[4];
    const float* Amat = (const float*)d_in[5];
    const float* Dvec = (const float*)d_in[6];
    const float* nBw  = (const float*)d_in[7];
    const float* nCw  = (const float*)d_in[8];
    const float* outw = (const float*)d_in[9];
    float* out        = (float*)d_out;

    void *px, *pz, *pbc, *pdt;
    void *puA, *pw1, *pxA, *pw3, *pyA, *pw4;
    cudaGetSymbolAddress(&px,  g_x);
    cudaGetSymbolAddress(&pz,  g_z);
    cudaGetSymbolAddress(&pbc, g_bc);
    cudaGetSymbolAddress(&pdt, g_dt);
    cudaGetSymbolAddress(&puA, g_uA);
    cudaGetSymbolAddress(&pw1, g_w1);
    cudaGetSymbolAddress(&pxA, g_xA);
    cudaGetSymbolAddress(&pw3, g_w3);
    cudaGetSymbolAddress(&pyA, g_yA);
    cudaGetSymbolAddress(&pw4, g_w4);

    cudaFuncSetAttribute(mma_gemm<1, 8>,  cudaFuncAttributeMaxDynamicSharedMemorySize, SMEM64);
    cudaFuncSetAttribute(mma_gemm<2, 16>, cudaFuncAttributeMaxDynamicSharedMemorySize, SMEM64);
    cudaFuncSetAttribute(mma_gemm<0, 8>,  cudaFuncAttributeMaxDynamicSharedMemorySize, SMEM64);

    // idx 0: conv w3 (biggest weight conversion)
    conv3_kernel<false, true ><<<dim3(DINNER/1024, BCCOLS),   256>>>(xpw, (__nv_bfloat16*)pw3, DINNER);
    // idx 1: conv w1
    conv3_kernel<false, false><<<dim3(DMODEL/1024, 2*DINNER), 256>>>(in_w, (__nv_bfloat16*)pw1, DMODEL);
    // idx 2: conv uA
    conv3_kernel<true,  false><<<dim3(DMODEL/1024, MTOK),     256>>>(u,    (__nv_bfloat16*)puA, DMODEL);
    // idx 3 (ncu profiles this): GEMM1 in_proj + silu/split (M=4096,N=4096,K3=3072)
    mma_gemm<1, 8><<<32 * 32, 256, SMEM64>>>(
        (const __nv_bfloat16*)puA, (const __nv_bfloat16*)pw1,
        (float*)px, (float*)pz, nullptr, 2*DINNER, 3*DMODEL, 32, 32);
    // idx 4: dtw fold rows for GEMM3
    convdt_kernel<<<dim3(DINNER/1024, 128), 256>>>(dtw, (__nv_bfloat16*)pw3);
    // idx 5: conv w4
    conv3_kernel<false, false><<<dim3(DINNER/1024, DMODEL),   256>>>(outw, (__nv_bfloat16*)pw4, DINNER);
    // idx 6: conv xA
    conv3_kernel<true,  false><<<dim3(DINNER/1024, MTOK),     256>>>((const float*)px, (__nv_bfloat16*)pxA, DINNER);
    // idx 7: GEMM3 x_proj + folded dt (M=4096, N=16512, K3=6144)
    mma_gemm<2, 16><<<32 * (NTOT3/128), 256, SMEM64>>>(
        (const __nv_bfloat16*)pxA, (const __nv_bfloat16*)pw3,
        (float*)pbc, (float*)pdt, dtb, BCCOLS, 3*DINNER, NTOT3/128, 32);
    // idx 8: prep (warp-per-(m,h), shuffle reductions)
    prep_kernel<<<dim3(MTOK, NHEADS/4), 128>>>(Amat, nBw, nCw);
    // idx 9: scan (R8-proven)
    scan_kernel<<<BATCH * NHEADS * 4, 32>>>();
    // idx 10: gate (emits bf16 split yA directly)
    ymul_kernel<<<(MTOK * DINNER) / 1024, 256>>>(Dvec);
    // idx 11: GEMM4 out_proj (M=4096, N=1024, K3=6144)
    mma_gemm<0, 8><<<32 * 8, 256, SMEM64>>>(
        (const __nv_bfloat16*)pyA, (const __nv_bfloat16*)pw4,
        out, nullptr, nullptr, DMODEL, 3*DINNER, 8, 32);

    (void)in_sizes; (void)n_in; (void)out_size;
}

// round 16
// speedup vs baseline: 1.1111x; 1.0011x over previous
#include <cuda_runtime.h>
#include <cuda_bf16.h>
#include <cstdint>
#include <math.h>

// ---------------- problem constants ----------------
#define BATCH   2
#define SEQL    2048
#define MTOK    (BATCH*SEQL)      // 4096
#define DMODEL  1024
#define DINNER  2048
#define NHEADS  32
#define HEADD   64
#define NSTATE  128
#define BCCOLS  16384             // 32 heads * 512 used cols
#define NTOT3   (BCCOLS + 128)    // GEMM3 N incl. folded dt block
#define XPROJ_ROWSTRIDE 513       // x_proj_w has 513 rows per head; last unused

// ---------------- fp32 scratch ----------------
__device__ float  g_x  [(size_t)MTOK*DINNER];     // silu(x)
__device__ float  g_z  [(size_t)MTOK*DINNER];     // raw z
__device__ float  g_dt [(size_t)MTOK*NHEADS];     // softplus(dt)  (folded into GEMM3)
__device__ float  g_bc [(size_t)MTOK*BCCOLS];     // raw BC (per-head 512 cols)
__device__ float2 g_a  [(size_t)BATCH*NHEADS*SEQL*NSTATE]; // abar
__device__ float2 g_u  [(size_t)BATCH*NHEADS*SEQL*NSTATE]; // u_in
__device__ float2 g_c  [(size_t)BATCH*NHEADS*SEQL*NSTATE]; // Cc
__device__ float  g_yp [(size_t)MTOK*NHEADS*4];   // 4-way partial y_red

// ---------------- bf16 hi/lo-split operand scratch (K' = 3K) ----------------
__device__ __nv_bfloat16 g_uA [(size_t)MTOK * 3*DMODEL];    // A' for GEMM1
__device__ __nv_bfloat16 g_w1 [(size_t)(2*DINNER) * 3*DMODEL];
__device__ __nv_bfloat16 g_xA [(size_t)MTOK * 3*DINNER];    // A' for GEMM3
__device__ __nv_bfloat16 g_w3 [(size_t)NTOT3 * 3*DINNER];   // remapped x_proj_w + dtw fold
__device__ __nv_bfloat16 g_yA [(size_t)MTOK * 3*DINNER];    // A' for GEMM4 (ymul-fused)
__device__ __nv_bfloat16 g_w4 [(size_t)DMODEL * 3*DINNER];

// ---------------- helpers ----------------
__device__ __forceinline__ float siluf(float v) { return v / (1.0f + expf(-v)); }
__device__ __forceinline__ float softplusf(float v) { return (v > 20.0f) ? v : log1pf(expf(v)); }

__device__ __forceinline__ uint32_t smem_u32(const void* p) {
    uint32_t a;
    asm("{ .reg .u64 t; cvta.to.shared.u64 t, %1; cvt.u32.u64 %0, t; }" : "=r"(a) : "l"(p));
    return a;
}

__device__ __forceinline__ void ldsm4(uint32_t* r, uint32_t addr) {
    asm volatile("ldmatrix.sync.aligned.m8n8.x4.shared.b16 {%0,%1,%2,%3}, [%4];"
        : "=r"(r[0]), "=r"(r[1]), "=r"(r[2]), "=r"(r[3]) : "r"(addr));
}

__device__ __forceinline__ void mma16816(float* d, const uint32_t* a, uint32_t b0, uint32_t b1) {
    asm volatile("mma.sync.aligned.m16n8k16.row.col.f32.bf16.bf16.f32 "
        "{%0,%1,%2,%3}, {%4,%5,%6,%7}, {%8,%9}, {%0,%1,%2,%3};"
        : "+f"(d[0]), "+f"(d[1]), "+f"(d[2]), "+f"(d[3])
        : "r"(a[0]), "r"(a[1]), "r"(a[2]), "r"(a[3]), "r"(b0), "r"(b1));
}

#define CP_ASYNC16(dst, src) \
    asm volatile("cp.async.cg.shared.global [%0], [%1], 16;" :: "r"(dst), "l"(src) : "memory")
#define CP_COMMIT() asm volatile("cp.async.commit_group;" ::: "memory")
#define CP_WAIT1()  asm volatile("cp.async.wait_group 1;" ::: "memory")

__device__ __forceinline__ void split_store3(__nv_bfloat16* base, size_t off, size_t seg,
                                             float v0, float v1) {
    __nv_bfloat16 h0 = __float2bfloat16(v0), h1 = __float2bfloat16(v1);
    __nv_bfloat16 l0 = __float2bfloat16(v0 - __bfloat162float(h0));
    __nv_bfloat16 l1 = __float2bfloat16(v1 - __bfloat162float(h1));
    __nv_bfloat162 hh = {h0, h1}, ll = {l0, l1};
    *(__nv_bfloat162*)(base + off)           = hh;   // hi
    *(__nv_bfloat162*)(base + off + seg)     = ll;   // lo
    *(__nv_bfloat162*)(base + off + 2 * seg) = hh;   // hi  (A-pattern [hi|lo|hi])
}

// ================= HMMA bf16 GEMM (R12-proven): BK=64, 3 stages x 32KB =================
// BM=BN=128, BK=64 (bf16, 128B rows), 256 threads (8 warps, 4M x 2N), warp tile 32x64
// via m16n8k16, 4 k16 sub-steps per kt. fp32 accumulate. 2 CTAs/SM (192KB smem total).
// Swizzle: chunk c ^ (row&7) on 128B rows; LDSM addr = (row*128 + ((row&7)<<4)) ^ kcs.
// EPI 0: plain fp32 store (ldc = N).
// EPI 1: in_proj: n0<DINNER -> C0=silu(v); else C1=v.
// EPI 2: x_proj: n0<BCCOLS -> C0=v (ldc BCCOLS); else dt fold:
//        C1[r*32+head] = softplus(v + bias[head]) for head<32.
#define STG64   32768                   // stage bytes: A 16KB + B 16KB
#define SMEM64  (3 * STG64)             // 96KB dynamic
template<int EPI, int SUP>
__global__ __launch_bounds__(256, 2)
void mma_gemm(const __nv_bfloat16* __restrict__ A, const __nv_bfloat16* __restrict__ W,
              float* __restrict__ C0, float* __restrict__ C1,
              const float* __restrict__ bias,
              int N, int K3, int nbN, int mblocks)
{
    extern __shared__ __align__(128) char sm[];    // 3 * 32KB
    const uint32_t sb = smem_u32(sm);
    const int tid  = threadIdx.x;
    const int lane = tid & 31, wid = tid >> 5;
    const int wm = wid & 3, wn = wid >> 2;

    // block swizzle: n-super-panels of width SUP, last panel may be narrower
    const int bid = blockIdx.x;
    const int per_super = mblocks * SUP;
    const int sup = bid / per_super;
    const int nb0 = sup * SUP;
    const int width = (SUP < nbN - nb0) ? SUP : (nbN - nb0);
    const int rem = bid - sup * per_super;
    const int m0 = (rem / width) * 128;
    const int n0 = (nb0 + rem % width) * 128;

    // producer indexing: 8 threads per 128B row; rows step by 32
    const int prow = tid >> 3;          // 0..31 (+32i)
    const int pc   = tid & 7;           // 16B chunk 0..7
    const uint32_t pd0 = (uint32_t)(prow * 128 + (((pc ^ (prow & 7))) << 4));
    const __nv_bfloat16* gA = A + (size_t)(m0 + prow) * K3 + pc * 8;
    const __nv_bfloat16* gB = W + (size_t)(n0 + prow) * K3 + pc * 8;

    const int KT = K3 >> 6;             // K3/64

    auto load_stage = [&](int s, int kt) {
        const int koff = kt * 64;
        const uint32_t dbase = sb + (uint32_t)s * STG64;
        #pragma unroll
        for (int i = 0; i < 4; i++) {
            const uint32_t d = pd0 + (uint32_t)(i * 32 * 128);   // rows step by 32
            CP_ASYNC16(dbase + d,         gA + (size_t)(i * 32) * K3 + koff);
            CP_ASYNC16(dbase + 16384 + d, gB + (size_t)(i * 32) * K3 + koff);
        }
    };

    // consumer: precomputed swizzled LDSM row offsets (ks-invariant part)
    uint32_t pa[2], pb[4];
    #pragma unroll
    for (int mt = 0; mt < 2; mt++) {
        const int row = wm * 32 + mt * 16 + (lane & 15);
        pa[mt] = (uint32_t)(row * 128) + ((uint32_t)(row & 7) << 4);
    }
    #pragma unroll
    for (int nbt = 0; nbt < 4; nbt++) {
        const int row = wn * 64 + nbt * 16 + (lane & 15);
        pb[nbt] = (uint32_t)(row * 128) + ((uint32_t)(row & 7) << 4);
    }
    const uint32_t kcs_base = ((uint32_t)(lane >> 4)) << 4;   // kc = ks*2 + (lane>>4)

    float acc[2][8][4];
    #pragma unroll
    for (int i = 0; i < 2; i++)
        #pragma unroll
        for (int j = 0; j < 8; j++)
            #pragma unroll
            for (int q = 0; q < 4; q++) acc[i][j][q] = 0.0f;

    load_stage(0, 0); CP_COMMIT();
    load_stage(1, 1); CP_COMMIT();

    int scur = 0, spre = 2;        // cycling stage counters (no modulo)
    for (int kt = 0; kt < KT; kt++) {
        CP_WAIT1();
        __syncthreads();
        if (kt + 2 < KT) load_stage(spre, kt + 2);
        CP_COMMIT();                       // empty group ok on tail

        const uint32_t abase = sb + (uint32_t)scur * STG64;
        const uint32_t bbase = abase + 16384;

        #pragma unroll
        for (int ks = 0; ks < 4; ks++) {
            uint32_t aF[2][4], bF[4][4];
            const uint32_t kcs = kcs_base + (uint32_t)(ks << 5);   // (ks*2)<<4
            #pragma unroll
            for (int mt = 0; mt < 2; mt++)
                ldsm4(aF[mt], abase + (pa[mt] ^ kcs));
            #pragma unroll
            for (int nbt = 0; nbt < 4; nbt++)
                ldsm4(bF[nbt], bbase + (pb[nbt] ^ kcs));
            #pragma unroll
            for (int mt = 0; mt < 2; mt++)
                #pragma unroll
                for (int nbt = 0; nbt < 4; nbt++) {
                    mma16816(acc[mt][2 * nbt + 0], aF[mt], bF[nbt][0], bF[nbt][2]);
                    mma16816(acc[mt][2 * nbt + 1], aF[mt], bF[nbt][1], bF[nbt][3]);
                }
        }
        scur = (scur == 2) ? 0 : scur + 1;
        spre = (spre == 2) ? 0 : spre + 1;
    }

    // epilogue
    #pragma unroll
    for (int mt = 0; mt < 2; mt++) {
        #pragma unroll
        for (int nt = 0; nt < 8; nt++) {
            const int r = m0 + wm * 32 + mt * 16 + (lane >> 2);
            const int c = n0 + wn * 64 + nt * 8 + (lane & 3) * 2;
            const float* a4 = acc[mt][nt];
            if (EPI == 0) {
                *(float2*)(C0 + (size_t)r * N + c)       = make_float2(a4[0], a4[1]);
                *(float2*)(C0 + (size_t)(r + 8) * N + c) = make_float2(a4[2], a4[3]);
            } else if (EPI == 1) {
                if (n0 < DINNER) {
                    *(float2*)(C0 + (size_t)r * DINNER + c)       = make_float2(siluf(a4[0]), siluf(a4[1]));
                    *(float2*)(C0 + (size_t)(r + 8) * DINNER + c) = make_float2(siluf(a4[2]), siluf(a4[3]));
                } else {
                    const int cc = c - DINNER;
                    *(float2*)(C1 + (size_t)r * DINNER + cc)       = make_float2(a4[0], a4[1]);
                    *(float2*)(C1 + (size_t)(r + 8) * DINNER + cc) = make_float2(a4[2], a4[3]);
                }
            } else { // EPI == 2
                if (n0 < BCCOLS) {
                    *(float2*)(C0 + (size_t)r * BCCOLS + c)       = make_float2(a4[0], a4[1]);
                    *(float2*)(C0 + (size_t)(r + 8) * BCCOLS + c) = make_float2(a4[2], a4[3]);
                } else {
                    const int head = c - BCCOLS;
                    if (head < NHEADS) {
                        const float b0 = bias[head];
                        C1[(size_t)r * NHEADS + head]       = softplusf(a4[0] + b0);
                        C1[(size_t)(r + 8) * NHEADS + head] = softplusf(a4[2] + b0);
                    }
                    if (head + 1 < NHEADS) {
                        const float b1 = bias[head + 1];
                        C1[(size_t)r * NHEADS + head + 1]       = softplusf(a4[1] + b1);
                        C1[(size_t)(r + 8) * NHEADS + head + 1] = softplusf(a4[3] + b1);
                    }
                }
            }
        }
    }
}

// ============== fp32 -> bf16 hi/lo split, K' = 3K ==============
// A-pattern: [hi | lo | hi]   W-pattern: [hi | hi | lo]
template<bool APAT, bool REMAP>
__global__ __launch_bounds__(256)
void conv3_kernel(const float* __restrict__ src, __nv_bfloat16* __restrict__ dst, int K)
{
    const int c4 = (blockIdx.x * 256 + threadIdx.x) * 4;
    const int row = blockIdx.y;
    const int srow = REMAP ? ((row >> 9) * XPROJ_ROWSTRIDE + (row & 511)) : row;
    float4 v = *(const float4*)(src + (size_t)srow * K + c4);
    __nv_bfloat16 h0 = __float2bfloat16(v.x), h1 = __float2bfloat16(v.y);
    __nv_bfloat16 h2 = __float2bfloat16(v.z), h3 = __float2bfloat16(v.w);
    __nv_bfloat16 l0 = __float2bfloat16(v.x - __bfloat162float(h0));
    __nv_bfloat16 l1 = __float2bfloat16(v.y - __bfloat162float(h1));
    __nv_bfloat16 l2 = __float2bfloat16(v.z - __bfloat162float(h2));
    __nv_bfloat16 l3 = __float2bfloat16(v.w - __bfloat162float(h3));
    __nv_bfloat162 hA = {h0, h1}, hB = {h2, h3};
    __nv_bfloat162 lA = {l0, l1}, lB = {l2, l3};
    __nv_bfloat162* d0 = (__nv_bfloat162*)(dst + (size_t)row * 3 * K + c4);
    __nv_bfloat162* d1 = (__nv_bfloat162*)(dst + (size_t)row * 3 * K + K + c4);
    __nv_bfloat162* d2 = (__nv_bfloat162*)(dst + (size_t)row * 3 * K + 2 * K + c4);
    d0[0] = hA; d0[1] = hB;
    if (APAT) { d1[0] = lA; d1[1] = lB; d2[0] = hA; d2[1] = hB; }
    else      { d1[0] = hA; d1[1] = hB; d2[0] = lA; d2[1] = lB; }
}

// dtw rows appended to g_w3 at rows [BCCOLS, BCCOLS+128): W-pattern, zero pad
__global__ __launch_bounds__(256)
void convdt_kernel(const float* __restrict__ dtw, __nv_bfloat16* __restrict__ dst)
{
    const int c4 = (blockIdx.x * 256 + threadIdx.x) * 4;
    const int r = blockIdx.y;
    __nv_bfloat16* drow = dst + (size_t)(BCCOLS + r) * 3 * DINNER;
    __nv_bfloat162 hA = {(__nv_bfloat16)0.f, (__nv_bfloat16)0.f}, hB = hA, lA = hA, lB = hA;
    if (r < NHEADS) {
        float4 v = *(const float4*)(dtw + (size_t)r * DINNER + c4);
        __nv_bfloat16 h0 = __float2bfloat16(v.x), h1 = __float2bfloat16(v.y);
        __nv_bfloat16 h2 = __float2bfloat16(v.z), h3 = __float2bfloat16(v.w);
        __nv_bfloat16 l0 = __float2bfloat16(v.x - __bfloat162float(h0));
        __nv_bfloat16 l1 = __float2bfloat16(v.y - __bfloat162float(h1));
        __nv_bfloat16 l2 = __float2bfloat16(v.z - __bfloat162float(h2));
        __nv_bfloat16 l3 = __float2bfloat16(v.w - __bfloat162float(h3));
        hA = {h0, h1}; hB = {h2, h3}; lA = {l0, l1}; lB = {l2, l3};
    }
    __nv_bfloat162* d0 = (__nv_bfloat162*)(drow + c4);
    __nv_bfloat162* d1 = (__nv_bfloat162*)(drow + DINNER + c4);
    __nv_bfloat162* d2 = (__nv_bfloat162*)(drow + 2 * DINNER + c4);
    d0[0] = hA; d0[1] = hB;
    d1[0] = hA; d1[1] = hB;
    d2[0] = lA; d2[1] = lB;
}

// ---------------- prep: warp per (m,h), shuffle reductions, zero barriers ----------------
__global__ __launch_bounds__(128, 8)
void prep_kernel(const float* __restrict__ A_, const float* __restrict__ nBw,
                 const float* __restrict__ nCw)
{
    const int m = blockIdx.x;
    const int h = blockIdx.y * 4 + (threadIdx.x >> 5);
    const int lane = threadIdx.x & 31;
    const int b = m >> 11;
    const int t = m & 2047;

    const float4* bcp = (const float4*)(g_bc + (size_t)m * BCCOLS + h * 512);
    float4 b0 = bcp[lane * 2],      b1 = bcp[lane * 2 + 1];
    float4 c0 = bcp[64 + lane * 2], c1 = bcp[64 + lane * 2 + 1];

    float sB = b0.x*b0.x + b0.y*b0.y + b0.z*b0.z + b0.w*b0.w
             + b1.x*b1.x + b1.y*b1.y + b1.z*b1.z + b1.w*b1.w;
    float sC = c0.x*c0.x + c0.y*c0.y + c0.z*c0.z + c0.w*c0.w
             + c1.x*c1.x + c1.y*c1.y + c1.z*c1.z + c1.w*c1.w;
    float2 xv = ((const float2*)(g_x + (size_t)m * DINNER + h * HEADD))[lane];
    float sx = xv.x + xv.y;

    #pragma unroll
    for (int off = 16; off; off >>= 1) {
        sB += __shfl_xor_sync(0xFFFFFFFFu, sB, off);
        sC += __shfl_xor_sync(0xFFFFFFFFu, sC, off);
        sx += __shfl_xor_sync(0xFFFFFFFFu, sx, off);
    }

    const float rB = rsqrtf(sB * (1.0f / 256.0f) + 1e-6f);
    const float rC = rsqrtf(sC * (1.0f / 256.0f) + 1e-6f);
    const float dt = g_dt[(size_t)m * NHEADS + h];
    const float hdt = 0.5f * dt;
    const float sdt = dt * sx;

    const int n0 = lane * 4;
    float2 Bv[4] = { {b0.x, b0.y}, {b0.z, b0.w}, {b1.x, b1.y}, {b1.z, b1.w} };
    float2 Cv[4] = { {c0.x, c0.y}, {c0.z, c0.w}, {c1.x, c1.y}, {c1.z, c1.w} };

    const float4* Avp = (const float4*)((const float2*)A_ + h * NSTATE + n0);
    float4 Av01 = Avp[0], Av23 = Avp[1];
    float2 Av[4] = { {Av01.x, Av01.y}, {Av01.z, Av01.w}, {Av23.x, Av23.y}, {Av23.z, Av23.w} };

    const float4* wBp = (const float4*)((const float2*)nBw + n0);
    const float4* wCp = (const float4*)((const float2*)nCw + n0);
    float4 wB01 = wBp[0], wB23 = wBp[1], wC01 = wCp[0], wC23 = wCp[1];
    float2 wB[4] = { {wB01.x, wB01.y}, {wB01.z, wB01.w}, {wB23.x, wB23.y}, {wB23.z, wB23.w} };
    float2 wC[4] = { {wC01.x, wC01.y}, {wC01.z, wC01.w}, {wC23.x, wC23.y}, {wC23.z, wC23.w} };

    float2 av[4], uv[4], cv[4];
    #pragma unroll
    for (int j = 0; j < 4; j++) {
        const float ztr = Av[j].x * hdt, zti = Av[j].y * hdt;
        const float dr = 1.0f - ztr, di = -zti;
        const float inv = 1.0f / (dr * dr + di * di);
        const float nr = 1.0f + ztr, ni = zti;
        av[j].x = (nr * dr + ni * di) * inv;
        av[j].y = (ni * dr - nr * di) * inv;
        const float pr = sdt * dr * inv, pi = -sdt * di * inv;
        const float Bcx = Bv[j].x * rB * wB[j].x, Bcy = Bv[j].y * rB * wB[j].y;
        uv[j].x = Bcx * pr - Bcy * pi;
        uv[j].y = Bcx * pi + Bcy * pr;
        cv[j].x = Cv[j].x * rC * wC[j].x;
        cv[j].y = Cv[j].y * rC * wC[j].y;
    }

    const size_t base = (((size_t)(b * NHEADS + h)) * SEQL + t) * NSTATE + n0;
    float4* ap = (float4*)&g_a[base];
    float4* up = (float4*)&g_u[base];
    float4* cp = (float4*)&g_c[base];
    ap[0] = make_float4(av[0].x, av[0].y, av[1].x, av[1].y);
    ap[1] = make_float4(av[2].x, av[2].y, av[3].x, av[3].y);
    up[0] = make_float4(uv[0].x, uv[0].y, uv[1].x, uv[1].y);
    up[1] = make_float4(uv[2].x, uv[2].y, uv[3].x, uv[3].y);
    cp[0] = make_float4(cv[0].x, cv[0].y, cv[1].x, cv[1].y);
    cp[1] = make_float4(cv[2].x, cv[2].y, cv[3].x, cv[3].y);
}

// ---------------- scan (R8-proven): 256 CTAs = 64 (b,h) x 4 n-quarters, 1 warp each ----------------
__global__ __launch_bounds__(32, 8)
void scan_kernel()
{
    const int bh = blockIdx.x >> 2;
    const int q  = blockIdx.x & 3;
    const int b = bh >> 5, h = bh & 31;
    const int lane = threadIdx.x;

    const size_t base = ((size_t)bh * SEQL) * NSTATE + q * 32 + lane;
    float hr = 0.0f, hi = 0.0f;

    __shared__ float rbuf[32][33];

    for (int t0 = 0; t0 < SEQL; t0 += 32) {
        #pragma unroll 8
        for (int tt = 0; tt < 32; tt++) {
            size_t idx = base + (size_t)(t0 + tt) * NSTATE;
            float2 a = g_a[idx];
            float2 u = g_u[idx];
            float2 c = g_c[idx];
            float nhr = fmaf(a.x, hr, fmaf(-a.y, hi, u.x));
            float nhi = fmaf(a.x, hi, fmaf( a.y, hr, u.y));
            hr = nhr; hi = nhi;
            rbuf[tt][lane] = c.x * hr - c.y * hi;
        }
        __syncwarp();
        float p = 0.0f;
        #pragma unroll
        for (int i = 0; i < 32; i++) p += rbuf[lane][i];
        g_yp[((size_t)(b * SEQL + t0 + lane) * NHEADS + h) * 4 + q] = p;
        __syncwarp();
    }
}

// ---------------- gate: yA = split( x * (y_red + D) * silu(z) ) ----------------
__global__ __launch_bounds__(256)
void ymul_kernel(const float* __restrict__ Dv)
{
    const int i4 = (blockIdx.x * 256 + threadIdx.x) * 4;
    const int m = i4 >> 11;
    const int d = i4 & 2047;
    const int h = d >> 6;
    float4 p = *(const float4*)&g_yp[((size_t)m * NHEADS + h) * 4];
    const float scale = (p.x + p.y + p.z + p.w) + Dv[h];
    float4 xv = *(const float4*)&g_x[(size_t)m * DINNER + d];
    float4 zv = *(const float4*)&g_z[(size_t)m * DINNER + d];
    float y0 = xv.x * scale * siluf(zv.x);
    float y1 = xv.y * scale * siluf(zv.y);
    float y2 = xv.z * scale * siluf(zv.z);
    float y3 = xv.w * scale * siluf(zv.w);
    split_store3(g_yA, (size_t)m * (3 * DINNER) + d,     DINNER, y0, y1);
    split_store3(g_yA, (size_t)m * (3 * DINNER) + d + 2, DINNER, y2, y3);
}

// ---------------- launch ----------------
extern "C" void kernel_launch(void* const* d_in, const int* in_sizes, int n_in,
                              void* d_out, int out_size)
{
    const float* u    = (const float*)d_in[0];
    const float* in_w = (const float*)d_in[1];
    const float* dtw  = (const float*)d_in[2];
    const float* dtb  = (const float*)d_in[3];
    const float* xpw  = (const float*)d_in[4];
    const float* Amat = (const float*)d_in[5];
    const float* Dvec = (const float*)d_in[6];
    const float* nBw  = (const float*)d_in[7];
    const float* nCw  = (const float*)d_in[8];
    const float* outw = (const float*)d_in[9];
    float* out        = (float*)d_out;

    void *px, *pz, *pbc, *pdt;
    void *puA, *pw1, *pxA, *pw3, *pyA, *pw4;
    cudaGetSymbolAddress(&px,  g_x);
    cudaGetSymbolAddress(&pz,  g_z);
    cudaGetSymbolAddress(&pbc, g_bc);
    cudaGetSymbolAddress(&pdt, g_dt);
    cudaGetSymbolAddress(&puA, g_uA);
    cudaGetSymbolAddress(&pw1, g_w1);
    cudaGetSymbolAddress(&pxA, g_xA);
    cudaGetSymbolAddress(&pw3, g_w3);
    cudaGetSymbolAddress(&pyA, g_yA);
    cudaGetSymbolAddress(&pw4, g_w4);

    cudaFuncSetAttribute(mma_gemm<1, 8>,  cudaFuncAttributeMaxDynamicSharedMemorySize, SMEM64);
    cudaFuncSetAttribute(mma_gemm<2, 16>, cudaFuncAttributeMaxDynamicSharedMemorySize, SMEM64);
    cudaFuncSetAttribute(mma_gemm<0, 8>,  cudaFuncAttributeMaxDynamicSharedMemorySize, SMEM64);

    // side stream + fork/join events (created once on the first, uncaptured, call;
    // reused by the capture call — GPU work is identical every call)
    static cudaStream_t s_side = nullptr;
    static cudaEvent_t  ev_fork = nullptr, ev_join = nullptr;
    if (s_side == nullptr) {
        cudaStreamCreateWithFlags(&s_side, cudaStreamNonBlocking);
        cudaEventCreateWithFlags(&ev_fork, cudaEventDisableTiming);
        cudaEventCreateWithFlags(&ev_join, cudaEventDisableTiming);
    }

    // ---- fork: side stream converts w3 + dt-fold + w4 (independent of GEMM1) ----
    cudaEventRecord(ev_fork, 0);
    cudaStreamWaitEvent(s_side, ev_fork, 0);
    conv3_kernel<false, true ><<<dim3(DINNER/1024, BCCOLS), 256, 0, s_side>>>(
        xpw, (__nv_bfloat16*)pw3, DINNER);
    convdt_kernel<<<dim3(DINNER/1024, 128), 256, 0, s_side>>>(dtw, (__nv_bfloat16*)pw3);
    conv3_kernel<false, false><<<dim3(DINNER/1024, DMODEL), 256, 0, s_side>>>(
        outw, (__nv_bfloat16*)pw4, DINNER);
    cudaEventRecord(ev_join, s_side);

    // ---- main stream: GEMM1 inputs, GEMM1, xA conversion (overlaps side stream) ----
    conv3_kernel<false, false><<<dim3(DMODEL/1024, 2*DINNER), 256>>>(in_w, (__nv_bfloat16*)pw1, DMODEL);
    conv3_kernel<true,  false><<<dim3(DMODEL/1024, MTOK),     256>>>(u,    (__nv_bfloat16*)puA, DMODEL);
    mma_gemm<1, 8><<<32 * 32, 256, SMEM64>>>(
        (const __nv_bfloat16*)puA, (const __nv_bfloat16*)pw1,
        (float*)px, (float*)pz, nullptr, 2*DINNER, 3*DMODEL, 32, 32);
    conv3_kernel<true,  false><<<dim3(DINNER/1024, MTOK),     256>>>((const float*)px, (__nv_bfloat16*)pxA, DINNER);

    // ---- join: w3/dt-fold/w4 must be complete before GEMM3 ----
    cudaStreamWaitEvent(0, ev_join, 0);

    // GEMM3: x_proj + folded dt (M=4096, N=16512, K3=6144)
    mma_gemm<2, 16><<<32 * (NTOT3/128), 256, SMEM64>>>(
        (const __nv_bfloat16*)pxA, (const __nv_bfloat16*)pw3,
        (float*)pbc, (float*)pdt, dtb, BCCOLS, 3*DINNER, NTOT3/128, 32);
    // prep (warp-per-(m,h), shuffle reductions)
    prep_kernel<<<dim3(MTOK, NHEADS/4), 128>>>(Amat, nBw, nCw);
    // scan
    scan_kernel<<<BATCH * NHEADS * 4, 32>>>();
    // gate (emits bf16 split yA directly)
    ymul_kernel<<<(MTOK * DINNER) / 1024, 256>>>(Dvec);
    // GEMM4: out_proj (M=4096, N=1024, K3=6144); w4 already joined before GEMM3
    mma_gemm<0, 8><<<32 * 8, 256, SMEM64>>>(
        (const __nv_bfloat16*)pyA, (const __nv_bfloat16*)pw4,
        out, nullptr, nullptr, DMODEL, 3*DINNER, 8, 32);

    (void)in_sizes; (void)n_in; (void)out_size;
}